// round 11
// baseline (speedup 1.0000x reference)
#include <cuda_runtime.h>
#include <cuda_fp16.h>
#include <cstdint>

// Problem constants
#define N_U   1024
#define BATCH 4096
#define H     10
#define INV1023 (1.0f / 1023.0f)

// ---------------------------------------------------------------------------
// Scratch (device globals)
// ---------------------------------------------------------------------------
__device__ float g_colpart[32][N_U];
__device__ float g_rowsum[N_U];
__device__ __align__(16) float g_F[N_U][12];      // padded; cols 10-11 stay 0
__device__ __align__(16) float g_G[N_U][12];
__device__ __align__(16) float g_IF[N_U][12];     // R_h*rowsum_i + F[i][h]
__device__ __align__(16) float g_JG[N_U][12];     // C_h*colsum_j + G[j][h]
__device__ __align__(16) float g_ACR[3][12];
__device__ __align__(256) float g_NW[N_U * N_U];  // new_weight [k][n]

// Split operands (fp16 bits). hi = fp16(x); lo = fp16(x - hi)
__device__ __align__(256) unsigned short g_Ahi[BATCH * N_U];
__device__ __align__(256) unsigned short g_Alo[BATCH * N_U];
__device__ __align__(256) unsigned short g_Bhi[N_U * N_U];       // [n][k]
__device__ __align__(256) unsigned short g_Blo[N_U * N_U];       // [n][k]

// ---------------------------------------------------------------------------
// Helpers
// ---------------------------------------------------------------------------
__device__ __forceinline__ uint32_t smem_u32(const void* p) {
    uint32_t a;
    asm("{ .reg .u64 t; cvta.to.shared.u64 t, %1; cvt.u32.u64 %0, t; }" : "=r"(a) : "l"(p));
    return a;
}

#define CP_ASYNC16(dst, src) \
    asm volatile("cp.async.cg.shared.global [%0], [%1], 16;" :: "r"(dst), "l"(src))
#define CP_COMMIT() asm volatile("cp.async.commit_group;")
#define CP_WAIT(n)  asm volatile("cp.async.wait_group %0;" :: "n"(n))

#define LDMATRIX_X4(r0, r1, r2, r3, addr) \
    asm volatile("ldmatrix.sync.aligned.m8n8.x4.shared.b16 {%0,%1,%2,%3}, [%4];" \
        : "=r"(r0), "=r"(r1), "=r"(r2), "=r"(r3) : "r"(addr))

#define MMA_F16F32(c0, c1, c2, c3, a0, a1, a2, a3, b0, b1) \
    asm volatile("mma.sync.aligned.m16n8k16.row.col.f32.f16.f16.f32 " \
        "{%0,%1,%2,%3}, {%4,%5,%6,%7}, {%8,%9}, {%0,%1,%2,%3};" \
        : "+f"(c0), "+f"(c1), "+f"(c2), "+f"(c3) \
        : "r"(a0), "r"(a1), "r"(a2), "r"(a3), "r"(b0), "r"(b1))

// ---------------------------------------------------------------------------
// Kernel 1 (fused, all-independent blocks): split X / colpart / rowsum / tables
// ---------------------------------------------------------------------------
__global__ void __launch_bounds__(256) prep_kernel(const float* __restrict__ X,
                                                   const float* __restrict__ W,
                                                   const float* __restrict__ W1,
                                                   const float* __restrict__ b1) {
    __shared__ float red[8];
    int b = blockIdx.x;
    int tid = threadIdx.x;
    if (b < 4096) {
        int gid = b * 256 + tid;
        int idx = gid * 4;
        float4 v = *(const float4*)(X + idx);
        __half hx = __float2half_rn(v.x), hy = __float2half_rn(v.y);
        __half hz = __float2half_rn(v.z), hw = __float2half_rn(v.w);
        __half lx = __float2half_rn(v.x - __half2float(hx));
        __half ly = __float2half_rn(v.y - __half2float(hy));
        __half lz = __float2half_rn(v.z - __half2float(hz));
        __half lw = __float2half_rn(v.w - __half2float(hw));
        uint32_t hi01 = (uint32_t)__half_as_ushort(hx) | ((uint32_t)__half_as_ushort(hy) << 16);
        uint32_t hi23 = (uint32_t)__half_as_ushort(hz) | ((uint32_t)__half_as_ushort(hw) << 16);
        uint32_t lo01 = (uint32_t)__half_as_ushort(lx) | ((uint32_t)__half_as_ushort(ly) << 16);
        uint32_t lo23 = (uint32_t)__half_as_ushort(lz) | ((uint32_t)__half_as_ushort(lw) << 16);
        *(uint2*)(g_Ahi + idx) = make_uint2(hi01, hi23);
        *(uint2*)(g_Alo + idx) = make_uint2(lo01, lo23);
    } else if (b < 4224) {
        int b2 = b - 4096;
        int rg  = b2 >> 2;
        int col = (b2 & 3) * 256 + tid;
        int r0  = rg * 32;
        float s = 0.f;
#pragma unroll
        for (int r = 0; r < 32; r++) s += W[(r0 + r) * N_U + col];
        g_colpart[rg][col] = s;
    } else if (b < 5248) {
        int row = b - 4224;
        float4 v = *(const float4*)(W + row * N_U + tid * 4);
        float s = v.x + v.y + v.z + v.w;
#pragma unroll
        for (int o = 16; o > 0; o >>= 1) s += __shfl_xor_sync(0xffffffffu, s, o);
        if ((tid & 31) == 0) red[tid >> 5] = s;
        __syncthreads();
        if (tid == 0) {
            float t = 0.f;
#pragma unroll
            for (int i = 0; i < 8; i++) t += red[i];
            g_rowsum[row] = t;
        }
    } else {
        int idx = (b - 5248) * 256 + tid;
        if (idx < N_U * H) {
            int i = idx / H, h = idx % H;
            float acc = 0.f;
#pragma unroll
            for (int t = 0; t < 10; t++) {
                float coef = W1[(3 + t) * H + h] + W1[(43 + t) * H + h]
                           - W1[(23 + t) * H + h] * INV1023;
                if ((i >> (9 - t)) & 1) acc += coef;
            }
            g_F[i][h] = acc;
        } else if (idx < 2 * N_U * H) {
            int r = idx - N_U * H;
            int j = r / H, h = r % H;
            float acc = b1[h];
#pragma unroll
            for (int s = 0; s < 10; s++) {
                float coef = W1[(13 + s) * H + h] + W1[(33 + s) * H + h]
                           - W1[(53 + s) * H + h] * INV1023;
                if ((j >> (9 - s)) & 1) acc += coef;
                acc += (512.f * INV1023) * (W1[(23 + s) * H + h] + W1[(53 + s) * H + h]);
            }
            g_G[j][h] = acc;
        } else if (idx < 2 * N_U * H + H) {
            int h = idx - 2 * N_U * H;
            g_ACR[0][h] = W1[h] - (W1[H + h] + W1[2 * H + h]) * INV1023;
            g_ACR[1][h] = W1[H + h] * INV1023;
            g_ACR[2][h] = W1[2 * H + h] * INV1023;
        }
    }
}

// ---------------------------------------------------------------------------
// Kernel 2: finish column sums; build folded tables
// ---------------------------------------------------------------------------
__global__ void __launch_bounds__(256) fold_kernel() {
    int b = blockIdx.x;
    int tid = threadIdx.x;
    if (b < 4) {
        int col = b * 256 + tid;
        float s = 0.f;
#pragma unroll
        for (int p = 0; p < 32; p++) s += g_colpart[p][col];
#pragma unroll
        for (int q = 0; q < 3; q++) {
            float4 c = ((const float4*)g_ACR[1])[q];
            float4 g = ((const float4*)g_G[col])[q];
            float4 r;
            r.x = fmaf(c.x, s, g.x);
            r.y = fmaf(c.y, s, g.y);
            r.z = fmaf(c.z, s, g.z);
            r.w = fmaf(c.w, s, g.w);
            ((float4*)g_JG[col])[q] = r;
        }
    } else {
        int i = (b - 4) * 256 + tid;
        float s = g_rowsum[i];
#pragma unroll
        for (int q = 0; q < 3; q++) {
            float4 c = ((const float4*)g_ACR[2])[q];
            float4 f = ((const float4*)g_F[i])[q];
            float4 r;
            r.x = fmaf(c.x, s, f.x);
            r.y = fmaf(c.y, s, f.y);
            r.z = fmaf(c.z, s, f.z);
            r.w = fmaf(c.w, s, f.w);
            ((float4*)g_IF[i])[q] = r;
        }
    }
}

// ---------------------------------------------------------------------------
// Per-cell MLP -> g_NW (R10 version, proven)
// ---------------------------------------------------------------------------
__global__ void __launch_bounds__(256) mlp_kernel(const float* __restrict__ W,
                                                  const float* __restrict__ W2,
                                                  const float* __restrict__ b2,
                                                  const float* __restrict__ W3,
                                                  const float* __restrict__ b3) {
    __shared__ __align__(16) float sW2T[H][12];
    __shared__ __align__(16) float sA[12];
    __shared__ __align__(16) float sIF[12];
    __shared__ float sB2[H], sW3[H];
    __shared__ float sb3;
    int tid = threadIdx.x;
    int i = blockIdx.x;

    if (tid < 120) {
        int k = tid / 12, h = tid % 12;
        sW2T[k][h] = (h < H) ? W2[h * H + k] : 0.f;
    }
    if (tid >= 128 && tid < 140) sA[tid - 128]  = g_ACR[0][tid - 128];
    if (tid >= 160 && tid < 172) sIF[tid - 160] = g_IF[i][tid - 160];
    if (tid < H) { sB2[tid] = b2[tid]; sW3[tid] = W3[tid * 21]; }
    if (tid == 0) sb3 = b3[0];
    __syncthreads();

    float w[4];
#pragma unroll
    for (int c = 0; c < 4; c++) w[c] = W[i * N_U + c * 256 + tid];

    float z[4][12];
#pragma unroll
    for (int q = 0; q < 3; q++) {
        float4 a = ((const float4*)sA)[q];
        float4 f = ((const float4*)sIF)[q];
#pragma unroll
        for (int c = 0; c < 4; c++) {
            int j = c * 256 + tid;
            float4 g = ((const float4*)g_JG[j])[q];
            float tx = f.x + g.x, ty = f.y + g.y, tz = f.z + g.z, tw = f.w + g.w;
            z[c][q * 4 + 0] = fmaxf(fmaf(a.x, w[c], tx), 0.f);
            z[c][q * 4 + 1] = fmaxf(fmaf(a.y, w[c], ty), 0.f);
            z[c][q * 4 + 2] = fmaxf(fmaf(a.z, w[c], tz), 0.f);
            z[c][q * 4 + 3] = fmaxf(fmaf(a.w, w[c], tw), 0.f);
        }
    }

    float upd[4] = {sb3, sb3, sb3, sb3};
#pragma unroll
    for (int k = 0; k < H; k++) {
        const float4* w4 = (const float4*)sW2T[k];
        float4 wa = w4[0], wb = w4[1];
        float2 wc = *(const float2*)&sW2T[k][8];
        float bk = sB2[k], w3k = sW3[k];
#pragma unroll
        for (int c = 0; c < 4; c++) {
            float y = bk;
            y = fmaf(z[c][0], wa.x, y);
            y = fmaf(z[c][1], wa.y, y);
            y = fmaf(z[c][2], wa.z, y);
            y = fmaf(z[c][3], wa.w, y);
            y = fmaf(z[c][4], wb.x, y);
            y = fmaf(z[c][5], wb.y, y);
            y = fmaf(z[c][6], wb.z, y);
            y = fmaf(z[c][7], wb.w, y);
            y = fmaf(z[c][8], wc.x, y);
            y = fmaf(z[c][9], wc.y, y);
            upd[c] = fmaf(fmaxf(y, 0.f), w3k, upd[c]);
        }
    }
#pragma unroll
    for (int c = 0; c < 4; c++) {
        int j = c * 256 + tid;
        g_NW[i * N_U + j] = w[c] + upd[c];
    }
}

// ---------------------------------------------------------------------------
// Transpose + fp16 split NW -> g_Bhi/g_Blo [n][k]
// ---------------------------------------------------------------------------
__global__ void __launch_bounds__(256) transpose_split_kernel() {
    __shared__ float tile[32][33];
    int bx = blockIdx.x, by = blockIdx.y;
    int tx = threadIdx.x, ty = threadIdx.y;           // 32 x 8
    int i0 = by * 32, j0 = bx * 32;
#pragma unroll
    for (int r = 0; r < 4; r++)
        tile[ty * 4 + r][tx] = g_NW[(i0 + ty * 4 + r) * N_U + j0 + tx];
    __syncthreads();
#pragma unroll
    for (int r = 0; r < 4; r++) {
        int j = j0 + ty * 4 + r;
        int i = i0 + tx;
        float v  = tile[tx][ty * 4 + r];
        __half h = __float2half_rn(v);
        __half l = __float2half_rn(v - __half2float(h));
        g_Bhi[j * N_U + i] = __half_as_ushort(h);
        g_Blo[j * N_U + i] = __half_as_ushort(l);
    }
}

// ---------------------------------------------------------------------------
// Hybrid GEMM: out = relu(X @ NW)
//   Warps 0-7 (256 thr): 3-pass fp16 tensor MMA, BM=96 rows [mt*96, mt*96+96)
//   Warps 8-9 (64 thr) : exact fp32 FFMA for 15 leftover rows/CTA
//                        rows [3552 + mt*15, +15) (guarded at 4096)
// Grid 37x4 = 148 CTAs, one wave. X rows for FFMA staged in smem.
// ---------------------------------------------------------------------------
#define BM 96
#define BN 256
#define BK 32
#define STAGES 4
#define AROW 40
#define ABYTES (BM * AROW * 2)           // 7680
#define BBYTES (BN * AROW * 2)           // 20480
#define STBYTES (ABYTES + BBYTES)        // 28160
#define XBYTES (15 * 1024 * 4)           // 61440
#define SMEM_GEMM (XBYTES + STAGES * STBYTES)   // 174080

__global__ void __launch_bounds__(320, 1) gemm_hybrid_kernel(const float* __restrict__ X,
                                                             float* __restrict__ out) {
    extern __shared__ char smem[];
    uint32_t sb = smem_u32(smem);
    int tid  = threadIdx.x;
    int wid  = tid >> 5;
    int lane = tid & 31;

    int mt = blockIdx.x % 37;
    int nt = blockIdx.x / 37;

    const int frow0 = 3552 + mt * 15;     // FFMA row base for this CTA

    const unsigned short* Aseg[3];
    const unsigned short* Bseg[3];
    Aseg[0] = g_Ahi;  Aseg[1] = g_Ahi;  Aseg[2] = g_Alo;
    Bseg[0] = g_Bhi + (size_t)(nt * BN) * N_U;
    Bseg[1] = g_Blo + (size_t)(nt * BN) * N_U;
    Bseg[2] = Bseg[0];

    const int ITERS = 96;

    auto load_stage = [&](int it, int st) {
        int seg = it >> 5;
        int k0  = (it & 31) * BK;
        uint32_t abase = sb + XBYTES + st * STBYTES;
        uint32_t bbase = abase + ABYTES;
        const unsigned short* Ag = Aseg[seg];
        const unsigned short* Bg = Bseg[seg];
#pragma unroll
        for (int q = 0; q < 2; q++) {                 // A: 384 chunks
            int chunk = tid + q * 256;
            if (chunk < BM * 4) {
                int row = chunk >> 2;
                int off = (chunk & 3) * 8;
                CP_ASYNC16(abase + row * (AROW * 2) + off * 2,
                           (const char*)(Ag + (size_t)(mt * BM + row) * N_U + k0 + off));
            }
        }
#pragma unroll
        for (int q = 0; q < 4; q++) {                 // B: 1024 chunks
            int chunk = tid + q * 256;
            int row = chunk >> 2;
            int off = (chunk & 3) * 8;
            CP_ASYNC16(bbase + row * (AROW * 2) + off * 2,
                       (const char*)(Bg + (size_t)row * N_U + k0 + off));
        }
    };

    // Prologue: stage FFMA X rows (group of stage 0), then stages 0..2
    if (tid < 256) {
#pragma unroll
        for (int q = 0; q < 15; q++) {
            int chunk = tid + q * 256;                // 3840 chunks
            int r   = chunk >> 8;                     // 0..14
            int off = (chunk & 255) * 16;             // bytes
            int grow = frow0 + r;
            if (grow > 4095) grow = 4095;
            CP_ASYNC16(sb + r * 4096 + off, (const char*)(X + (size_t)grow * N_U) + off);
        }
        load_stage(0, 0);
    }
    CP_COMMIT();
    if (tid < 256) load_stage(1, 1);
    CP_COMMIT();
    if (tid < 256) load_stage(2, 2);
    CP_COMMIT();

    if (wid < 8) {
        // ------------------- tensor path -------------------
        int nw = wid;
        float c[6][4][4];
#pragma unroll
        for (int f = 0; f < 6; f++)
#pragma unroll
            for (int n = 0; n < 4; n++)
#pragma unroll
                for (int q = 0; q < 4; q++) c[f][n][q] = 0.f;

        int lrow = lane & 15;
        int lcol = (lane >> 4) * 16;

        for (int i = 0; i < ITERS; i++) {
            CP_WAIT(2);
            __syncthreads();

            int nx = i + STAGES - 1;
            if (nx < ITERS) load_stage(nx, nx & (STAGES - 1));
            CP_COMMIT();

            int st = i & (STAGES - 1);
            uint32_t abase = sb + XBYTES + st * STBYTES;
            uint32_t bbase = abase + ABYTES;

#pragma unroll
            for (int ks = 0; ks < 2; ks++) {
                uint32_t a[6][4];
#pragma unroll
                for (int f = 0; f < 6; f++)
                    LDMATRIX_X4(a[f][0], a[f][1], a[f][2], a[f][3],
                        abase + (f * 16 + lrow) * (AROW * 2) + ks * 32 + lcol);
                uint32_t b[4][2];
#pragma unroll
                for (int g = 0; g < 2; g++) {
                    uint32_t r0, r1, r2, r3;
                    LDMATRIX_X4(r0, r1, r2, r3,
                        bbase + (nw * 32 + g * 16 + lrow) * (AROW * 2) + ks * 32 + lcol);
                    b[2 * g][0] = r0;  b[2 * g][1] = r2;
                    b[2 * g + 1][0] = r1;  b[2 * g + 1][1] = r3;
                }
#pragma unroll
                for (int f = 0; f < 6; f++)
#pragma unroll
                    for (int n = 0; n < 4; n++)
                        MMA_F16F32(c[f][n][0], c[f][n][1], c[f][n][2], c[f][n][3],
                                   a[f][0], a[f][1], a[f][2], a[f][3], b[n][0], b[n][1]);
            }
        }

        // Epilogue (rows < 3552, no guard)
        int cbase = nt * BN + nw * 32 + (lane & 3) * 2;
#pragma unroll
        for (int f = 0; f < 6; f++) {
            int r = mt * BM + f * 16 + (lane >> 2);
#pragma unroll
            for (int n = 0; n < 4; n++) {
                int cc = cbase + n * 8;
                float2 v0, v1;
                v0.x = fmaxf(c[f][n][0], 0.f);
                v0.y = fmaxf(c[f][n][1], 0.f);
                v1.x = fmaxf(c[f][n][2], 0.f);
                v1.y = fmaxf(c[f][n][3], 0.f);
                *(float2*)(out + (size_t)r * N_U + cc)       = v0;
                *(float2*)(out + (size_t)(r + 8) * N_U + cc) = v1;
            }
        }
    } else {
        // ------------------- FFMA path (exact fp32) -------------------
        int ft = tid - 256;                // 0..63
        int colg = nt * BN + ft * 4;
        const float* sX = (const float*)smem;
        float acc[15][4];
#pragma unroll
        for (int r = 0; r < 15; r++)
#pragma unroll
            for (int q = 0; q < 4; q++) acc[r][q] = 0.f;

        for (int i = 0; i < ITERS; i++) {
            __syncthreads();
            int kb = (i * 1024) / 96;
            int ke = ((i + 1) * 1024) / 96;
            for (int k = kb; k < ke; k++) {
                float4 nw4 = *(const float4*)(g_NW + (size_t)k * N_U + colg);
#pragma unroll
                for (int r = 0; r < 15; r++) {
                    float x = sX[r * 1024 + k];
                    acc[r][0] = fmaf(x, nw4.x, acc[r][0]);
                    acc[r][1] = fmaf(x, nw4.y, acc[r][1]);
                    acc[r][2] = fmaf(x, nw4.z, acc[r][2]);
                    acc[r][3] = fmaf(x, nw4.w, acc[r][3]);
                }
            }
        }

#pragma unroll
        for (int r = 0; r < 15; r++) {
            int row = frow0 + r;
            if (row < BATCH) {
                float4 v;
                v.x = fmaxf(acc[r][0], 0.f);
                v.y = fmaxf(acc[r][1], 0.f);
                v.z = fmaxf(acc[r][2], 0.f);
                v.w = fmaxf(acc[r][3], 0.f);
                *(float4*)(out + (size_t)row * N_U + colg) = v;
            }
        }
    }
}

// ---------------------------------------------------------------------------
// Row softmax in-place
// ---------------------------------------------------------------------------
__global__ void __launch_bounds__(256) softmax_kernel(float* __restrict__ out) {
    __shared__ float redm[8];
    __shared__ float reds[8];
    __shared__ float bval[2];
    int row = blockIdx.x, tid = threadIdx.x;
    int lane = tid & 31, wid = tid >> 5;

    float4 v = *(float4*)(out + row * N_U + tid * 4);
    float m = fmaxf(fmaxf(v.x, v.y), fmaxf(v.z, v.w));
#pragma unroll
    for (int o = 16; o > 0; o >>= 1) m = fmaxf(m, __shfl_xor_sync(0xffffffffu, m, o));
    if (lane == 0) redm[wid] = m;
    __syncthreads();
    if (tid == 0) {
        float t = redm[0];
#pragma unroll
        for (int i = 1; i < 8; i++) t = fmaxf(t, redm[i]);
        bval[0] = t;
    }
    __syncthreads();
    m = bval[0];
    v.x = __expf(v.x - m); v.y = __expf(v.y - m);
    v.z = __expf(v.z - m); v.w = __expf(v.w - m);
    float s = v.x + v.y + v.z + v.w;
#pragma unroll
    for (int o = 16; o > 0; o >>= 1) s += __shfl_xor_sync(0xffffffffu, s, o);
    if (lane == 0) reds[wid] = s;
    __syncthreads();
    if (tid == 0) {
        float t = 0.f;
#pragma unroll
        for (int i = 0; i < 8; i++) t += reds[i];
        bval[1] = 1.f / t;
    }
    __syncthreads();
    float inv = bval[1];
    v.x *= inv; v.y *= inv; v.z *= inv; v.w *= inv;
    *(float4*)(out + row * N_U + tid * 4) = v;
}

// ---------------------------------------------------------------------------
// Entry point
// ---------------------------------------------------------------------------
extern "C" void kernel_launch(void* const* d_in, const int* in_sizes, int n_in,
                              void* d_out, int out_size) {
    const float* X      = (const float*)d_in[0];
    const float* weight = (const float*)d_in[1];
    const float* W1     = (const float*)d_in[3];
    const float* b1     = (const float*)d_in[4];
    const float* W2     = (const float*)d_in[5];
    const float* b2     = (const float*)d_in[6];
    const float* W3     = (const float*)d_in[7];
    const float* b3     = (const float*)d_in[8];
    float* out = (float*)d_out;

    static bool attr_done = false;
    if (!attr_done) {
        cudaFuncSetAttribute(gemm_hybrid_kernel,
                             cudaFuncAttributeMaxDynamicSharedMemorySize, SMEM_GEMM);
        attr_done = true;
    }

    prep_kernel<<<5329, 256>>>(X, weight, W1, b1);                      // 1
    fold_kernel<<<8, 256>>>();                                          // 2
    mlp_kernel<<<N_U, 256>>>(weight, W2, b2, W3, b3);                   // 3
    transpose_split_kernel<<<dim3(32, 32), dim3(32, 8)>>>();            // 4
    gemm_hybrid_kernel<<<148, 320, SMEM_GEMM>>>(X, out);                // 5
    softmax_kernel<<<BATCH, 256>>>(out);                                // 6
}

// round 12
// speedup vs baseline: 1.7882x; 1.7882x over previous
#include <cuda_runtime.h>
#include <cuda_fp16.h>
#include <cstdint>

// Problem constants
#define N_U   1024
#define BATCH 4096
#define H     10
#define INV1023 (1.0f / 1023.0f)

// ---------------------------------------------------------------------------
// Scratch (device globals)
// ---------------------------------------------------------------------------
__device__ float g_colpart[32][N_U];
__device__ float g_rowpart[4][N_U];
__device__ __align__(16) float g_F[N_U][12];      // padded; cols 10-11 stay 0
__device__ __align__(16) float g_G[N_U][12];
__device__ __align__(16) float g_IF[N_U][12];     // R_h*rowsum_i + F[i][h]
__device__ __align__(16) float g_JG[N_U][12];     // C_h*colsum_j + G[j][h]
__device__ __align__(16) float g_ACR[3][12];

// fp16 split operands. A: [m][k]. B: NW split kept in natural [k][n] layout!
__device__ __align__(256) unsigned short g_Ahi[BATCH * N_U];   // 8 MB
__device__ __align__(256) unsigned short g_Alo[BATCH * N_U];   // 8 MB
__device__ __align__(256) unsigned short g_Bh[N_U * N_U];      // 2 MB  [k][n] hi
__device__ __align__(256) unsigned short g_Bl[N_U * N_U];      // 2 MB  [k][n] lo

// ---------------------------------------------------------------------------
// Helpers
// ---------------------------------------------------------------------------
__device__ __forceinline__ uint32_t smem_u32(const void* p) {
    uint32_t a;
    asm("{ .reg .u64 t; cvta.to.shared.u64 t, %1; cvt.u32.u64 %0, t; }" : "=r"(a) : "l"(p));
    return a;
}

#define CP_ASYNC16(dst, src) \
    asm volatile("cp.async.cg.shared.global [%0], [%1], 16;" :: "r"(dst), "l"(src))
#define CP_COMMIT() asm volatile("cp.async.commit_group;")
#define CP_WAIT(n)  asm volatile("cp.async.wait_group %0;" :: "n"(n))

#define LDMATRIX_X4(r0, r1, r2, r3, addr) \
    asm volatile("ldmatrix.sync.aligned.m8n8.x4.shared.b16 {%0,%1,%2,%3}, [%4];" \
        : "=r"(r0), "=r"(r1), "=r"(r2), "=r"(r3) : "r"(addr))

#define LDMATRIX_X4_T(r0, r1, r2, r3, addr) \
    asm volatile("ldmatrix.sync.aligned.m8n8.x4.trans.shared.b16 {%0,%1,%2,%3}, [%4];" \
        : "=r"(r0), "=r"(r1), "=r"(r2), "=r"(r3) : "r"(addr))

#define MMA_F16F32(c0, c1, c2, c3, a0, a1, a2, a3, b0, b1) \
    asm volatile("mma.sync.aligned.m16n8k16.row.col.f32.f16.f16.f32 " \
        "{%0,%1,%2,%3}, {%4,%5,%6,%7}, {%8,%9}, {%0,%1,%2,%3};" \
        : "+f"(c0), "+f"(c1), "+f"(c2), "+f"(c3) \
        : "r"(a0), "r"(a1), "r"(a2), "r"(a3), "r"(b0), "r"(b1))

// ---------------------------------------------------------------------------
// Kernel 1 (fused): blocks
//   [0,4096)    : split X -> g_Ahi/g_Alo
//   [4096,4224) : W strip: column partial sums AND row partial sums (W read once)
//   [4224,4305) : precompute F/G/ACR tables
// ---------------------------------------------------------------------------
__global__ void __launch_bounds__(256) prep_kernel(const float* __restrict__ X,
                                                   const float* __restrict__ W,
                                                   const float* __restrict__ W1,
                                                   const float* __restrict__ b1) {
    __shared__ float rred[32][9];
    int b = blockIdx.x;
    int tid = threadIdx.x;
    if (b < 4096) {
        int gid = b * 256 + tid;
        int idx = gid * 4;
        float4 v = *(const float4*)(X + idx);
        __half hx = __float2half_rn(v.x), hy = __float2half_rn(v.y);
        __half hz = __float2half_rn(v.z), hw = __float2half_rn(v.w);
        __half lx = __float2half_rn(v.x - __half2float(hx));
        __half ly = __float2half_rn(v.y - __half2float(hy));
        __half lz = __float2half_rn(v.z - __half2float(hz));
        __half lw = __float2half_rn(v.w - __half2float(hw));
        uint32_t hi01 = (uint32_t)__half_as_ushort(hx) | ((uint32_t)__half_as_ushort(hy) << 16);
        uint32_t hi23 = (uint32_t)__half_as_ushort(hz) | ((uint32_t)__half_as_ushort(hw) << 16);
        uint32_t lo01 = (uint32_t)__half_as_ushort(lx) | ((uint32_t)__half_as_ushort(ly) << 16);
        uint32_t lo23 = (uint32_t)__half_as_ushort(lz) | ((uint32_t)__half_as_ushort(lw) << 16);
        *(uint2*)(g_Ahi + idx) = make_uint2(hi01, hi23);
        *(uint2*)(g_Alo + idx) = make_uint2(lo01, lo23);
    } else if (b < 4224) {
        int b2 = b - 4096;
        int rg = b2 >> 2;                 // 32-row strip index
        int cq = b2 & 3;                  // 256-col quarter
        int col = cq * 256 + tid;
        int r0  = rg * 32;
        int wl = tid & 31, wr = tid >> 5;
        float s = 0.f;
#pragma unroll
        for (int r = 0; r < 32; r++) {
            float w = W[(r0 + r) * N_U + col];
            s += w;
            float rs = w;
#pragma unroll
            for (int o = 16; o > 0; o >>= 1) rs += __shfl_xor_sync(0xffffffffu, rs, o);
            if (wl == 0) rred[r][wr] = rs;
        }
        g_colpart[rg][col] = s;
        __syncthreads();
        if (tid < 32) {
            float t = 0.f;
#pragma unroll
            for (int p = 0; p < 8; p++) t += rred[tid][p];
            g_rowpart[cq][r0 + tid] = t;
        }
    } else {
        int idx = (b - 4224) * 256 + tid;
        if (idx < N_U * H) {
            int i = idx / H, h = idx % H;
            float acc = 0.f;
#pragma unroll
            for (int t = 0; t < 10; t++) {
                float coef = W1[(3 + t) * H + h] + W1[(43 + t) * H + h]
                           - W1[(23 + t) * H + h] * INV1023;
                if ((i >> (9 - t)) & 1) acc += coef;
            }
            g_F[i][h] = acc;
        } else if (idx < 2 * N_U * H) {
            int r = idx - N_U * H;
            int j = r / H, h = r % H;
            float acc = b1[h];
#pragma unroll
            for (int s = 0; s < 10; s++) {
                float coef = W1[(13 + s) * H + h] + W1[(33 + s) * H + h]
                           - W1[(53 + s) * H + h] * INV1023;
                if ((j >> (9 - s)) & 1) acc += coef;
                acc += (512.f * INV1023) * (W1[(23 + s) * H + h] + W1[(53 + s) * H + h]);
            }
            g_G[j][h] = acc;
        } else if (idx < 2 * N_U * H + H) {
            int h = idx - 2 * N_U * H;
            g_ACR[0][h] = W1[h] - (W1[H + h] + W1[2 * H + h]) * INV1023;
            g_ACR[1][h] = W1[H + h] * INV1023;
            g_ACR[2][h] = W1[2 * H + h] * INV1023;
        }
    }
}

// ---------------------------------------------------------------------------
// Kernel 2: finish sums; build folded tables
// ---------------------------------------------------------------------------
__global__ void __launch_bounds__(256) fold_kernel() {
    int b = blockIdx.x;
    int tid = threadIdx.x;
    if (b < 4) {
        int col = b * 256 + tid;
        float s = 0.f;
#pragma unroll
        for (int p = 0; p < 32; p++) s += g_colpart[p][col];
#pragma unroll
        for (int q = 0; q < 3; q++) {
            float4 c = ((const float4*)g_ACR[1])[q];
            float4 g = ((const float4*)g_G[col])[q];
            float4 r;
            r.x = fmaf(c.x, s, g.x);
            r.y = fmaf(c.y, s, g.y);
            r.z = fmaf(c.z, s, g.z);
            r.w = fmaf(c.w, s, g.w);
            ((float4*)g_JG[col])[q] = r;
        }
    } else {
        int i = (b - 4) * 256 + tid;
        float s = g_rowpart[0][i] + g_rowpart[1][i] + g_rowpart[2][i] + g_rowpart[3][i];
#pragma unroll
        for (int q = 0; q < 3; q++) {
            float4 c = ((const float4*)g_ACR[2])[q];
            float4 f = ((const float4*)g_F[i])[q];
            float4 r;
            r.x = fmaf(c.x, s, f.x);
            r.y = fmaf(c.y, s, f.y);
            r.z = fmaf(c.z, s, f.z);
            r.w = fmaf(c.w, s, f.w);
            ((float4*)g_IF[i])[q] = r;
        }
    }
}

// ---------------------------------------------------------------------------
// Per-cell MLP -> writes fp16 hi/lo split of new_weight DIRECTLY in [k][n]
// layout (coalesced; no transpose kernel, no fp32 NW roundtrip).
// ---------------------------------------------------------------------------
__global__ void __launch_bounds__(256) mlp_kernel(const float* __restrict__ W,
                                                  const float* __restrict__ W2,
                                                  const float* __restrict__ b2,
                                                  const float* __restrict__ W3,
                                                  const float* __restrict__ b3) {
    __shared__ __align__(16) float sW2T[H][12];
    __shared__ __align__(16) float sA[12];
    __shared__ __align__(16) float sIF[12];
    __shared__ float sB2[H], sW3[H];
    __shared__ float sb3;
    int tid = threadIdx.x;
    int i = blockIdx.x;

    if (tid < 120) {
        int k = tid / 12, h = tid % 12;
        sW2T[k][h] = (h < H) ? W2[h * H + k] : 0.f;
    }
    if (tid >= 128 && tid < 140) sA[tid - 128]  = g_ACR[0][tid - 128];
    if (tid >= 160 && tid < 172) sIF[tid - 160] = g_IF[i][tid - 160];
    if (tid < H) { sB2[tid] = b2[tid]; sW3[tid] = W3[tid * 21]; }
    if (tid == 0) sb3 = b3[0];
    __syncthreads();

    float w[4];
#pragma unroll
    for (int c = 0; c < 4; c++) w[c] = W[i * N_U + c * 256 + tid];

    float z[4][12];
#pragma unroll
    for (int q = 0; q < 3; q++) {
        float4 a = ((const float4*)sA)[q];
        float4 f = ((const float4*)sIF)[q];
#pragma unroll
        for (int c = 0; c < 4; c++) {
            int j = c * 256 + tid;
            float4 g = ((const float4*)g_JG[j])[q];
            float tx = f.x + g.x, ty = f.y + g.y, tz = f.z + g.z, tw = f.w + g.w;
            z[c][q * 4 + 0] = fmaxf(fmaf(a.x, w[c], tx), 0.f);
            z[c][q * 4 + 1] = fmaxf(fmaf(a.y, w[c], ty), 0.f);
            z[c][q * 4 + 2] = fmaxf(fmaf(a.z, w[c], tz), 0.f);
            z[c][q * 4 + 3] = fmaxf(fmaf(a.w, w[c], tw), 0.f);
        }
    }

    float upd[4] = {sb3, sb3, sb3, sb3};
#pragma unroll
    for (int k = 0; k < H; k++) {
        const float4* w4 = (const float4*)sW2T[k];
        float4 wa = w4[0], wb = w4[1];
        float2 wc = *(const float2*)&sW2T[k][8];
        float bk = sB2[k], w3k = sW3[k];
#pragma unroll
        for (int c = 0; c < 4; c++) {
            float y = bk;
            y = fmaf(z[c][0], wa.x, y);
            y = fmaf(z[c][1], wa.y, y);
            y = fmaf(z[c][2], wa.z, y);
            y = fmaf(z[c][3], wa.w, y);
            y = fmaf(z[c][4], wb.x, y);
            y = fmaf(z[c][5], wb.y, y);
            y = fmaf(z[c][6], wb.z, y);
            y = fmaf(z[c][7], wb.w, y);
            y = fmaf(z[c][8], wc.x, y);
            y = fmaf(z[c][9], wc.y, y);
            upd[c] = fmaf(fmaxf(y, 0.f), w3k, upd[c]);
        }
    }
#pragma unroll
    for (int c = 0; c < 4; c++) {
        int j = c * 256 + tid;
        float v = w[c] + upd[c];
        __half h = __float2half_rn(v);
        __half l = __float2half_rn(v - __half2float(h));
        g_Bh[(size_t)i * N_U + j] = __half_as_ushort(h);
        g_Bl[(size_t)i * N_U + j] = __half_as_ushort(l);
    }
}

// ---------------------------------------------------------------------------
// GEMM: out = relu( Ahi*Bh + Ahi*Bl + Alo*Bh ), fp16 mma.sync f32-acc.
// B kept in [k][n] layout; smem B rows padded to 528B; ldmatrix.x4.trans.
// BM=112, BN=256 -> 37x4 = 148 CTAs, one balanced wave.
// 256 threads, 8 warps: each warp 112 rows x 32 cols (7x4 frags).
// ---------------------------------------------------------------------------
#define BM 112
#define BN 256
#define BK 32
#define STAGES 4
#define AROW 40                           // A smem row: 40 fp16 = 80B
#define BROW 528                          // B smem row: 512B payload + 16B pad
#define ABYTES (BM * AROW * 2)            // 8960
#define BBYTES (BK * BROW)                // 16896
#define STBYTES (ABYTES + BBYTES)         // 25856
#define SMEM_GEMM (STAGES * STBYTES)      // 103424

__global__ void __launch_bounds__(256, 1) gemm_mma_kernel(float* __restrict__ out) {
    extern __shared__ char smem[];
    uint32_t sb = smem_u32(smem);
    int tid  = threadIdx.x;
    int wid  = tid >> 5;
    int lane = tid & 31;

    int mt = blockIdx.x % 37;
    int nt = blockIdx.x / 37;
    int nw = wid;

    const unsigned short* Aseg[3];
    Aseg[0] = g_Ahi;  Aseg[1] = g_Ahi;  Aseg[2] = g_Alo;
    // B segments: 0 -> Bh, 1 -> Bl, 2 -> Bh  ([k][n], col offset nt*256)

    float c[7][4][4];
#pragma unroll
    for (int f = 0; f < 7; f++)
#pragma unroll
        for (int n = 0; n < 4; n++)
#pragma unroll
            for (int q = 0; q < 4; q++) c[f][n][q] = 0.f;

    const int ITERS = 96;

    auto load_stage = [&](int it, int st) {
        int seg = it >> 5;
        int k0  = (it & 31) * BK;
        uint32_t abase = sb + st * STBYTES;
        uint32_t bbase = abase + ABYTES;
        const unsigned short* Ag = Aseg[seg];
        const unsigned short* Bg = (seg == 1) ? g_Bl : g_Bh;
#pragma unroll
        for (int q = 0; q < 2; q++) {                 // A: 448 chunks
            int chunk = tid + q * 256;
            if (chunk < BM * 4) {
                int row = chunk >> 2;
                int off = (chunk & 3) * 8;
                int grow = mt * BM + row;
                if (grow > 4095) grow = 4095;
                CP_ASYNC16(abase + row * (AROW * 2) + off * 2,
                           (const char*)(Ag + (size_t)grow * N_U + k0 + off));
            }
        }
#pragma unroll
        for (int q = 0; q < 4; q++) {                 // B: 1024 chunks (32 k x 32)
            int chunk = tid + q * 256;
            int krow = chunk >> 5;
            int off  = (chunk & 31) * 16;             // bytes within 512B row
            CP_ASYNC16(bbase + krow * BROW + off,
                       (const char*)(Bg + (size_t)(k0 + krow) * N_U + nt * BN) + off);
        }
    };

#pragma unroll
    for (int s = 0; s < STAGES - 1; s++) {
        load_stage(s, s);
        CP_COMMIT();
    }

    int lrow = lane & 15;
    int lcol = (lane >> 4) * 16;

    for (int i = 0; i < ITERS; i++) {
        CP_WAIT(2);
        __syncthreads();

        int nx = i + STAGES - 1;
        if (nx < ITERS) load_stage(nx, nx & (STAGES - 1));
        CP_COMMIT();

        int st = i & (STAGES - 1);
        uint32_t abase = sb + st * STBYTES;
        uint32_t bbase = abase + ABYTES;

#pragma unroll
        for (int ks = 0; ks < 2; ks++) {
            uint32_t a[7][4];
#pragma unroll
            for (int f = 0; f < 7; f++)
                LDMATRIX_X4(a[f][0], a[f][1], a[f][2], a[f][3],
                    abase + (f * 16 + lrow) * (AROW * 2) + ks * 32 + lcol);
            // B via trans ldmatrix on [k][n]: rows addressed by k.
            // x4 trans at (k16 x n16): r0=(n0-7,k0-7) r1=(n0-7,k8-15)
            //                          r2=(n8-15,k0-7) r3=(n8-15,k8-15)
            uint32_t b[4][2];
#pragma unroll
            for (int g = 0; g < 2; g++) {
                uint32_t r0, r1, r2, r3;
                LDMATRIX_X4_T(r0, r1, r2, r3,
                    bbase + (ks * 16 + lrow) * BROW + nw * 64 + g * 32 + lcol);
                b[2 * g][0] = r0;  b[2 * g][1] = r1;
                b[2 * g + 1][0] = r2;  b[2 * g + 1][1] = r3;
            }
#pragma unroll
            for (int f = 0; f < 7; f++)
#pragma unroll
                for (int n = 0; n < 4; n++)
                    MMA_F16F32(c[f][n][0], c[f][n][1], c[f][n][2], c[f][n][3],
                               a[f][0], a[f][1], a[f][2], a[f][3], b[n][0], b[n][1]);
        }
    }

    // Epilogue: relu + guarded store
    int cbase = nt * BN + nw * 32 + (lane & 3) * 2;
#pragma unroll
    for (int f = 0; f < 7; f++) {
        int r = mt * BM + f * 16 + (lane >> 2);
#pragma unroll
        for (int n = 0; n < 4; n++) {
            int cc = cbase + n * 8;
            if (r < BATCH) {
                float2 v0;
                v0.x = fmaxf(c[f][n][0], 0.f);
                v0.y = fmaxf(c[f][n][1], 0.f);
                *(float2*)(out + (size_t)r * N_U + cc) = v0;
            }
            if (r + 8 < BATCH) {
                float2 v1;
                v1.x = fmaxf(c[f][n][2], 0.f);
                v1.y = fmaxf(c[f][n][3], 0.f);
                *(float2*)(out + (size_t)(r + 8) * N_U + cc) = v1;
            }
        }
    }
}

// ---------------------------------------------------------------------------
// Row softmax in-place
// ---------------------------------------------------------------------------
__global__ void __launch_bounds__(256) softmax_kernel(float* __restrict__ out) {
    __shared__ float redm[8];
    __shared__ float reds[8];
    __shared__ float bval[2];
    int row = blockIdx.x, tid = threadIdx.x;
    int lane = tid & 31, wid = tid >> 5;

    float4 v = *(float4*)(out + row * N_U + tid * 4);
    float m = fmaxf(fmaxf(v.x, v.y), fmaxf(v.z, v.w));
#pragma unroll
    for (int o = 16; o > 0; o >>= 1) m = fmaxf(m, __shfl_xor_sync(0xffffffffu, m, o));
    if (lane == 0) redm[wid] = m;
    __syncthreads();
    if (tid == 0) {
        float t = redm[0];
#pragma unroll
        for (int i = 1; i < 8; i++) t = fmaxf(t, redm[i]);
        bval[0] = t;
    }
    __syncthreads();
    m = bval[0];
    v.x = __expf(v.x - m); v.y = __expf(v.y - m);
    v.z = __expf(v.z - m); v.w = __expf(v.w - m);
    float s = v.x + v.y + v.z + v.w;
#pragma unroll
    for (int o = 16; o > 0; o >>= 1) s += __shfl_xor_sync(0xffffffffu, s, o);
    if (lane == 0) reds[wid] = s;
    __syncthreads();
    if (tid == 0) {
        float t = 0.f;
#pragma unroll
        for (int i = 0; i < 8; i++) t += reds[i];
        bval[1] = 1.f / t;
    }
    __syncthreads();
    float inv = bval[1];
    v.x *= inv; v.y *= inv; v.z *= inv; v.w *= inv;
    *(float4*)(out + row * N_U + tid * 4) = v;
}

// ---------------------------------------------------------------------------
// Entry point
// ---------------------------------------------------------------------------
extern "C" void kernel_launch(void* const* d_in, const int* in_sizes, int n_in,
                              void* d_out, int out_size) {
    const float* X      = (const float*)d_in[0];
    const float* weight = (const float*)d_in[1];
    const float* W1     = (const float*)d_in[3];
    const float* b1     = (const float*)d_in[4];
    const float* W2     = (const float*)d_in[5];
    const float* b2     = (const float*)d_in[6];
    const float* W3     = (const float*)d_in[7];
    const float* b3     = (const float*)d_in[8];
    float* out = (float*)d_out;

    static bool attr_done = false;
    if (!attr_done) {
        cudaFuncSetAttribute(gemm_mma_kernel,
                             cudaFuncAttributeMaxDynamicSharedMemorySize, SMEM_GEMM);
        attr_done = true;
    }

    prep_kernel<<<4305, 256>>>(X, weight, W1, b1);                      // 1
    fold_kernel<<<8, 256>>>();                                          // 2
    mlp_kernel<<<N_U, 256>>>(weight, W2, b2, W3, b3);                   // 3
    gemm_mma_kernel<<<148, 256, SMEM_GEMM>>>(out);                      // 4
    softmax_kernel<<<BATCH, 256>>>(out);                                // 5
}

// round 13
// speedup vs baseline: 1.8165x; 1.0159x over previous
#include <cuda_runtime.h>
#include <cuda_fp16.h>
#include <cstdint>

// Problem constants
#define N_U   1024
#define BATCH 4096
#define H     10
#define INV1023 (1.0f / 1023.0f)

// ---------------------------------------------------------------------------
// Scratch (device globals)
// ---------------------------------------------------------------------------
__device__ float g_colpart[32][N_U];
__device__ float g_rowpart[4][N_U];
__device__ __align__(16) float g_F[N_U][12];
__device__ __align__(16) float g_G[N_U][12];
__device__ __align__(16) float g_IF[N_U][12];
__device__ __align__(16) float g_JG[N_U][12];
__device__ __align__(16) float g_ACR[3][12];

// fp16 split operands. A: [m][k]. B: [k][n] (natural layout, trans-ldmatrix)
__device__ __align__(256) unsigned short g_Ahi[BATCH * N_U];
__device__ __align__(256) unsigned short g_Alo[BATCH * N_U];
__device__ __align__(256) unsigned short g_Bh[N_U * N_U];
__device__ __align__(256) unsigned short g_Bl[N_U * N_U];

// ---------------------------------------------------------------------------
// Helpers
// ---------------------------------------------------------------------------
__device__ __forceinline__ uint32_t smem_u32(const void* p) {
    uint32_t a;
    asm("{ .reg .u64 t; cvta.to.shared.u64 t, %1; cvt.u32.u64 %0, t; }" : "=r"(a) : "l"(p));
    return a;
}

#define CP_ASYNC16(dst, src) \
    asm volatile("cp.async.cg.shared.global [%0], [%1], 16;" :: "r"(dst), "l"(src))
#define CP_COMMIT() asm volatile("cp.async.commit_group;")
#define CP_WAIT(n)  asm volatile("cp.async.wait_group %0;" :: "n"(n))

#define LDMATRIX_X4(r0, r1, r2, r3, addr) \
    asm volatile("ldmatrix.sync.aligned.m8n8.x4.shared.b16 {%0,%1,%2,%3}, [%4];" \
        : "=r"(r0), "=r"(r1), "=r"(r2), "=r"(r3) : "r"(addr))

#define LDMATRIX_X4_T(r0, r1, r2, r3, addr) \
    asm volatile("ldmatrix.sync.aligned.m8n8.x4.trans.shared.b16 {%0,%1,%2,%3}, [%4];" \
        : "=r"(r0), "=r"(r1), "=r"(r2), "=r"(r3) : "r"(addr))

#define MMA_F16F32(c0, c1, c2, c3, a0, a1, a2, a3, b0, b1) \
    asm volatile("mma.sync.aligned.m16n8k16.row.col.f32.f16.f16.f32 " \
        "{%0,%1,%2,%3}, {%4,%5,%6,%7}, {%8,%9}, {%0,%1,%2,%3};" \
        : "+f"(c0), "+f"(c1), "+f"(c2), "+f"(c3) \
        : "r"(a0), "r"(a1), "r"(a2), "r"(a3), "r"(b0), "r"(b1))

// ---------------------------------------------------------------------------
// Kernel 1 (fused): split X / W strip sums (col+row, W read once) / tables
// ---------------------------------------------------------------------------
__global__ void __launch_bounds__(256) prep_kernel(const float* __restrict__ X,
                                                   const float* __restrict__ W,
                                                   const float* __restrict__ W1,
                                                   const float* __restrict__ b1) {
    __shared__ float rred[32][9];
    int b = blockIdx.x;
    int tid = threadIdx.x;
    if (b < 4096) {
        int gid = b * 256 + tid;
        int idx = gid * 4;
        float4 v = *(const float4*)(X + idx);
        __half hx = __float2half_rn(v.x), hy = __float2half_rn(v.y);
        __half hz = __float2half_rn(v.z), hw = __float2half_rn(v.w);
        __half lx = __float2half_rn(v.x - __half2float(hx));
        __half ly = __float2half_rn(v.y - __half2float(hy));
        __half lz = __float2half_rn(v.z - __half2float(hz));
        __half lw = __float2half_rn(v.w - __half2float(hw));
        uint32_t hi01 = (uint32_t)__half_as_ushort(hx) | ((uint32_t)__half_as_ushort(hy) << 16);
        uint32_t hi23 = (uint32_t)__half_as_ushort(hz) | ((uint32_t)__half_as_ushort(hw) << 16);
        uint32_t lo01 = (uint32_t)__half_as_ushort(lx) | ((uint32_t)__half_as_ushort(ly) << 16);
        uint32_t lo23 = (uint32_t)__half_as_ushort(lz) | ((uint32_t)__half_as_ushort(lw) << 16);
        *(uint2*)(g_Ahi + idx) = make_uint2(hi01, hi23);
        *(uint2*)(g_Alo + idx) = make_uint2(lo01, lo23);
    } else if (b < 4224) {
        int b2 = b - 4096;
        int rg = b2 >> 2;
        int cq = b2 & 3;
        int col = cq * 256 + tid;
        int r0  = rg * 32;
        int wl = tid & 31, wr = tid >> 5;
        float s = 0.f;
#pragma unroll
        for (int r = 0; r < 32; r++) {
            float w = W[(r0 + r) * N_U + col];
            s += w;
            float rs = w;
#pragma unroll
            for (int o = 16; o > 0; o >>= 1) rs += __shfl_xor_sync(0xffffffffu, rs, o);
            if (wl == 0) rred[r][wr] = rs;
        }
        g_colpart[rg][col] = s;
        __syncthreads();
        if (tid < 32) {
            float t = 0.f;
#pragma unroll
            for (int p = 0; p < 8; p++) t += rred[tid][p];
            g_rowpart[cq][r0 + tid] = t;
        }
    } else {
        int idx = (b - 4224) * 256 + tid;
        if (idx < N_U * H) {
            int i = idx / H, h = idx % H;
            float acc = 0.f;
#pragma unroll
            for (int t = 0; t < 10; t++) {
                float coef = W1[(3 + t) * H + h] + W1[(43 + t) * H + h]
                           - W1[(23 + t) * H + h] * INV1023;
                if ((i >> (9 - t)) & 1) acc += coef;
            }
            g_F[i][h] = acc;
        } else if (idx < 2 * N_U * H) {
            int r = idx - N_U * H;
            int j = r / H, h = r % H;
            float acc = b1[h];
#pragma unroll
            for (int s = 0; s < 10; s++) {
                float coef = W1[(13 + s) * H + h] + W1[(33 + s) * H + h]
                           - W1[(53 + s) * H + h] * INV1023;
                if ((j >> (9 - s)) & 1) acc += coef;
                acc += (512.f * INV1023) * (W1[(23 + s) * H + h] + W1[(53 + s) * H + h]);
            }
            g_G[j][h] = acc;
        } else if (idx < 2 * N_U * H + H) {
            int h = idx - 2 * N_U * H;
            g_ACR[0][h] = W1[h] - (W1[H + h] + W1[2 * H + h]) * INV1023;
            g_ACR[1][h] = W1[H + h] * INV1023;
            g_ACR[2][h] = W1[2 * H + h] * INV1023;
        }
    }
}

// ---------------------------------------------------------------------------
// Kernel 2: finish sums; build folded tables
// ---------------------------------------------------------------------------
__global__ void __launch_bounds__(256) fold_kernel() {
    int b = blockIdx.x;
    int tid = threadIdx.x;
    if (b < 4) {
        int col = b * 256 + tid;
        float s = 0.f;
#pragma unroll
        for (int p = 0; p < 32; p++) s += g_colpart[p][col];
#pragma unroll
        for (int q = 0; q < 3; q++) {
            float4 c = ((const float4*)g_ACR[1])[q];
            float4 g = ((const float4*)g_G[col])[q];
            float4 r;
            r.x = fmaf(c.x, s, g.x);
            r.y = fmaf(c.y, s, g.y);
            r.z = fmaf(c.z, s, g.z);
            r.w = fmaf(c.w, s, g.w);
            ((float4*)g_JG[col])[q] = r;
        }
    } else {
        int i = (b - 4) * 256 + tid;
        float s = g_rowpart[0][i] + g_rowpart[1][i] + g_rowpart[2][i] + g_rowpart[3][i];
#pragma unroll
        for (int q = 0; q < 3; q++) {
            float4 c = ((const float4*)g_ACR[2])[q];
            float4 f = ((const float4*)g_F[i])[q];
            float4 r;
            r.x = fmaf(c.x, s, f.x);
            r.y = fmaf(c.y, s, f.y);
            r.z = fmaf(c.z, s, f.z);
            r.w = fmaf(c.w, s, f.w);
            ((float4*)g_IF[i])[q] = r;
        }
    }
}

// ---------------------------------------------------------------------------
// Per-cell MLP -> fp16 hi/lo split of new_weight directly in [k][n]
// ---------------------------------------------------------------------------
__global__ void __launch_bounds__(256) mlp_kernel(const float* __restrict__ W,
                                                  const float* __restrict__ W2,
                                                  const float* __restrict__ b2,
                                                  const float* __restrict__ W3,
                                                  const float* __restrict__ b3) {
    __shared__ __align__(16) float sW2T[H][12];
    __shared__ __align__(16) float sA[12];
    __shared__ __align__(16) float sIF[12];
    __shared__ float sB2[H], sW3[H];
    __shared__ float sb3;
    int tid = threadIdx.x;
    int i = blockIdx.x;

    if (tid < 120) {
        int k = tid / 12, h = tid % 12;
        sW2T[k][h] = (h < H) ? W2[h * H + k] : 0.f;
    }
    if (tid >= 128 && tid < 140) sA[tid - 128]  = g_ACR[0][tid - 128];
    if (tid >= 160 && tid < 172) sIF[tid - 160] = g_IF[i][tid - 160];
    if (tid < H) { sB2[tid] = b2[tid]; sW3[tid] = W3[tid * 21]; }
    if (tid == 0) sb3 = b3[0];
    __syncthreads();

    float w[4];
#pragma unroll
    for (int c = 0; c < 4; c++) w[c] = W[i * N_U + c * 256 + tid];

    float z[4][12];
#pragma unroll
    for (int q = 0; q < 3; q++) {
        float4 a = ((const float4*)sA)[q];
        float4 f = ((const float4*)sIF)[q];
#pragma unroll
        for (int c = 0; c < 4; c++) {
            int j = c * 256 + tid;
            float4 g = ((const float4*)g_JG[j])[q];
            float tx = f.x + g.x, ty = f.y + g.y, tz = f.z + g.z, tw = f.w + g.w;
            z[c][q * 4 + 0] = fmaxf(fmaf(a.x, w[c], tx), 0.f);
            z[c][q * 4 + 1] = fmaxf(fmaf(a.y, w[c], ty), 0.f);
            z[c][q * 4 + 2] = fmaxf(fmaf(a.z, w[c], tz), 0.f);
            z[c][q * 4 + 3] = fmaxf(fmaf(a.w, w[c], tw), 0.f);
        }
    }

    float upd[4] = {sb3, sb3, sb3, sb3};
#pragma unroll
    for (int k = 0; k < H; k++) {
        const float4* w4 = (const float4*)sW2T[k];
        float4 wa = w4[0], wb = w4[1];
        float2 wc = *(const float2*)&sW2T[k][8];
        float bk = sB2[k], w3k = sW3[k];
#pragma unroll
        for (int c = 0; c < 4; c++) {
            float y = bk;
            y = fmaf(z[c][0], wa.x, y);
            y = fmaf(z[c][1], wa.y, y);
            y = fmaf(z[c][2], wa.z, y);
            y = fmaf(z[c][3], wa.w, y);
            y = fmaf(z[c][4], wb.x, y);
            y = fmaf(z[c][5], wb.y, y);
            y = fmaf(z[c][6], wb.z, y);
            y = fmaf(z[c][7], wb.w, y);
            y = fmaf(z[c][8], wc.x, y);
            y = fmaf(z[c][9], wc.y, y);
            upd[c] = fmaf(fmaxf(y, 0.f), w3k, upd[c]);
        }
    }
#pragma unroll
    for (int c = 0; c < 4; c++) {
        int j = c * 256 + tid;
        float v = w[c] + upd[c];
        __half h = __float2half_rn(v);
        __half l = __float2half_rn(v - __half2float(h));
        g_Bh[(size_t)i * N_U + j] = __half_as_ushort(h);
        g_Bl[(size_t)i * N_U + j] = __half_as_ushort(l);
    }
}

// ---------------------------------------------------------------------------
// GEMM: out = relu( Ahi*Bh + Ahi*Bl + Alo*Bh ), 512 threads / 16 warps.
// Warp layout: nw = wid&7 (cols nw*32); m-half = wid>>3 (frags 0-3 / 4-6).
// SMSP balance: warps {w, w+4, w+8, w+12} share an SMSP -> 2x 4-frag + 2x 3-frag.
// BM=112, BN=256, grid 37x4 = 148 CTAs (one wave). 4-stage cp.async.
// ---------------------------------------------------------------------------
#define BM 112
#define BN 256
#define BK 32
#define STAGES 4
#define AROW 40                           // A smem row: 80B
#define BROW 528                          // B smem row: 512B + 16B pad
#define ABYTES (BM * AROW * 2)            // 8960
#define BBYTES (BK * BROW)                // 16896
#define STBYTES (ABYTES + BBYTES)         // 25856
#define SMEM_GEMM (STAGES * STBYTES)      // 103424
#define ITERS 96

__device__ __forceinline__ void gemm_load_stage(uint32_t sb, int tid, int mt, int nt,
                                                int it, int st) {
    int seg = it >> 5;
    int k0  = (it & 31) * BK;
    uint32_t abase = sb + st * STBYTES;
    uint32_t bbase = abase + ABYTES;
    const unsigned short* Ag = (seg == 2) ? g_Alo : g_Ahi;
    const unsigned short* Bg = (seg == 1) ? g_Bl : g_Bh;
    if (tid < BM * 4) {                               // A: 448 16B chunks
        int row = tid >> 2;
        int off = (tid & 3) * 8;
        int grow = mt * BM + row;
        if (grow > 4095) grow = 4095;
        CP_ASYNC16(abase + row * (AROW * 2) + off * 2,
                   (const char*)(Ag + (size_t)grow * N_U + k0 + off));
    }
#pragma unroll
    for (int q = 0; q < 2; q++) {                     // B: 1024 16B chunks
        int chunk = tid + q * 512;
        int krow = chunk >> 5;
        int off  = (chunk & 31) * 16;
        CP_ASYNC16(bbase + krow * BROW + off,
                   (const char*)(Bg + (size_t)(k0 + krow) * N_U + nt * BN) + off);
    }
}

template <int FR, int FBASE>
__device__ __forceinline__ void gemm_main(uint32_t sb, int tid, int lane, int nw,
                                          int mt, int nt, float* __restrict__ out) {
    float c[FR][4][4];
#pragma unroll
    for (int f = 0; f < FR; f++)
#pragma unroll
        for (int n = 0; n < 4; n++)
#pragma unroll
            for (int q = 0; q < 4; q++) c[f][n][q] = 0.f;

    int lrow = lane & 15;
    int lcol = (lane >> 4) * 16;

    for (int i = 0; i < ITERS; i++) {
        CP_WAIT(2);
        __syncthreads();

        int nx = i + STAGES - 1;
        if (nx < ITERS) gemm_load_stage(sb, tid, mt, nt, nx, nx & (STAGES - 1));
        CP_COMMIT();

        int st = i & (STAGES - 1);
        uint32_t abase = sb + st * STBYTES;
        uint32_t bbase = abase + ABYTES;

#pragma unroll
        for (int ks = 0; ks < 2; ks++) {
            uint32_t a[FR][4];
#pragma unroll
            for (int f = 0; f < FR; f++)
                LDMATRIX_X4(a[f][0], a[f][1], a[f][2], a[f][3],
                    abase + ((FBASE + f) * 16 + lrow) * (AROW * 2) + ks * 32 + lcol);
            uint32_t b[4][2];
#pragma unroll
            for (int g = 0; g < 2; g++) {
                uint32_t r0, r1, r2, r3;
                LDMATRIX_X4_T(r0, r1, r2, r3,
                    bbase + (ks * 16 + lrow) * BROW + nw * 64 + g * 32 + lcol);
                b[2 * g][0] = r0;  b[2 * g][1] = r1;
                b[2 * g + 1][0] = r2;  b[2 * g + 1][1] = r3;
            }
#pragma unroll
            for (int f = 0; f < FR; f++)
#pragma unroll
                for (int n = 0; n < 4; n++)
                    MMA_F16F32(c[f][n][0], c[f][n][1], c[f][n][2], c[f][n][3],
                               a[f][0], a[f][1], a[f][2], a[f][3], b[n][0], b[n][1]);
        }
    }

    // Epilogue: relu + guarded store
    int cbase = nt * BN + nw * 32 + (lane & 3) * 2;
#pragma unroll
    for (int f = 0; f < FR; f++) {
        int r = mt * BM + (FBASE + f) * 16 + (lane >> 2);
#pragma unroll
        for (int n = 0; n < 4; n++) {
            int cc = cbase + n * 8;
            if (r < BATCH) {
                float2 v0;
                v0.x = fmaxf(c[f][n][0], 0.f);
                v0.y = fmaxf(c[f][n][1], 0.f);
                *(float2*)(out + (size_t)r * N_U + cc) = v0;
            }
            if (r + 8 < BATCH) {
                float2 v1;
                v1.x = fmaxf(c[f][n][2], 0.f);
                v1.y = fmaxf(c[f][n][3], 0.f);
                *(float2*)(out + (size_t)(r + 8) * N_U + cc) = v1;
            }
        }
    }
}

__global__ void __launch_bounds__(512, 1) gemm_mma_kernel(float* __restrict__ out) {
    extern __shared__ char smem[];
    uint32_t sb = smem_u32(smem);
    int tid  = threadIdx.x;
    int wid  = tid >> 5;
    int lane = tid & 31;

    int mt = blockIdx.x % 37;
    int nt = blockIdx.x / 37;
    int nw = wid & 7;

#pragma unroll
    for (int s = 0; s < STAGES - 1; s++) {
        gemm_load_stage(sb, tid, mt, nt, s, s);
        CP_COMMIT();
    }

    if (wid < 8) gemm_main<4, 0>(sb, tid, lane, nw, mt, nt, out);
    else         gemm_main<3, 4>(sb, tid, lane, nw, mt, nt, out);
}

// ---------------------------------------------------------------------------
// Row softmax in-place
// ---------------------------------------------------------------------------
__global__ void __launch_bounds__(256) softmax_kernel(float* __restrict__ out) {
    __shared__ float redm[8];
    __shared__ float reds[8];
    __shared__ float bval[2];
    int row = blockIdx.x, tid = threadIdx.x;
    int lane = tid & 31, wid = tid >> 5;

    float4 v = *(float4*)(out + row * N_U + tid * 4);
    float m = fmaxf(fmaxf(v.x, v.y), fmaxf(v.z, v.w));
#pragma unroll
    for (int o = 16; o > 0; o >>= 1) m = fmaxf(m, __shfl_xor_sync(0xffffffffu, m, o));
    if (lane == 0) redm[wid] = m;
    __syncthreads();
    if (tid == 0) {
        float t = redm[0];
#pragma unroll
        for (int i = 1; i < 8; i++) t = fmaxf(t, redm[i]);
        bval[0] = t;
    }
    __syncthreads();
    m = bval[0];
    v.x = __expf(v.x - m); v.y = __expf(v.y - m);
    v.z = __expf(v.z - m); v.w = __expf(v.w - m);
    float s = v.x + v.y + v.z + v.w;
#pragma unroll
    for (int o = 16; o > 0; o >>= 1) s += __shfl_xor_sync(0xffffffffu, s, o);
    if (lane == 0) reds[wid] = s;
    __syncthreads();
    if (tid == 0) {
        float t = 0.f;
#pragma unroll
        for (int i = 0; i < 8; i++) t += reds[i];
        bval[1] = 1.f / t;
    }
    __syncthreads();
    float inv = bval[1];
    v.x *= inv; v.y *= inv; v.z *= inv; v.w *= inv;
    *(float4*)(out + row * N_U + tid * 4) = v;
}

// ---------------------------------------------------------------------------
// Entry point
// ---------------------------------------------------------------------------
extern "C" void kernel_launch(void* const* d_in, const int* in_sizes, int n_in,
                              void* d_out, int out_size) {
    const float* X      = (const float*)d_in[0];
    const float* weight = (const float*)d_in[1];
    const float* W1     = (const float*)d_in[3];
    const float* b1     = (const float*)d_in[4];
    const float* W2     = (const float*)d_in[5];
    const float* b2     = (const float*)d_in[6];
    const float* W3     = (const float*)d_in[7];
    const float* b3     = (const float*)d_in[8];
    float* out = (float*)d_out;

    static bool attr_done = false;
    if (!attr_done) {
        cudaFuncSetAttribute(gemm_mma_kernel,
                             cudaFuncAttributeMaxDynamicSharedMemorySize, SMEM_GEMM);
        attr_done = true;
    }

    prep_kernel<<<4305, 256>>>(X, weight, W1, b1);                      // 1
    fold_kernel<<<8, 256>>>();                                          // 2
    mlp_kernel<<<N_U, 256>>>(weight, W2, b2, W3, b3);                   // 3
    gemm_mma_kernel<<<148, 512, SMEM_GEMM>>>(out);                      // 4
    softmax_kernel<<<BATCH, 256>>>(out);                                // 5
}

// round 14
// speedup vs baseline: 2.1203x; 1.1672x over previous
#include <cuda_runtime.h>
#include <cuda_fp16.h>
#include <cstdint>

// Problem constants
#define N_U   1024
#define BATCH 4096
#define H     10
#define INV1023 (1.0f / 1023.0f)

// ---------------------------------------------------------------------------
// Scratch (device globals)
// ---------------------------------------------------------------------------
__device__ float g_colpart[32][N_U];
__device__ float g_rowpart[4][N_U];
__device__ __align__(16) float g_F[N_U][12];
__device__ __align__(16) float g_G[N_U][12];
__device__ __align__(16) float g_IF[N_U][12];
__device__ __align__(16) float g_JG[N_U][12];
__device__ __align__(16) float g_ACR[3][12];

// fp16 split operands. A: [m][k]. B: [k][n]
__device__ __align__(256) unsigned short g_Ahi[BATCH * N_U];
__device__ __align__(256) unsigned short g_Alo[BATCH * N_U];
__device__ __align__(256) unsigned short g_Bh[N_U * N_U];
__device__ __align__(256) unsigned short g_Bl[N_U * N_U];

// ---------------------------------------------------------------------------
// Helpers
// ---------------------------------------------------------------------------
__device__ __forceinline__ uint32_t smem_u32(const void* p) {
    uint32_t a;
    asm("{ .reg .u64 t; cvta.to.shared.u64 t, %1; cvt.u32.u64 %0, t; }" : "=r"(a) : "l"(p));
    return a;
}

#define CP_ASYNC16(dst, src) \
    asm volatile("cp.async.cg.shared.global [%0], [%1], 16;" :: "r"(dst), "l"(src))
#define CP_COMMIT() asm volatile("cp.async.commit_group;")
#define CP_WAIT(n)  asm volatile("cp.async.wait_group %0;" :: "n"(n))

#define LDMATRIX_X4(r0, r1, r2, r3, addr) \
    asm volatile("ldmatrix.sync.aligned.m8n8.x4.shared.b16 {%0,%1,%2,%3}, [%4];" \
        : "=r"(r0), "=r"(r1), "=r"(r2), "=r"(r3) : "r"(addr))

#define LDMATRIX_X4_T(r0, r1, r2, r3, addr) \
    asm volatile("ldmatrix.sync.aligned.m8n8.x4.trans.shared.b16 {%0,%1,%2,%3}, [%4];" \
        : "=r"(r0), "=r"(r1), "=r"(r2), "=r"(r3) : "r"(addr))

#define MMA_F16F32(c0, c1, c2, c3, a0, a1, a2, a3, b0, b1) \
    asm volatile("mma.sync.aligned.m16n8k16.row.col.f32.f16.f16.f32 " \
        "{%0,%1,%2,%3}, {%4,%5,%6,%7}, {%8,%9}, {%0,%1,%2,%3};" \
        : "+f"(c0), "+f"(c1), "+f"(c2), "+f"(c3) \
        : "r"(a0), "r"(a1), "r"(a2), "r"(a3), "r"(b0), "r"(b1))

// ---------------------------------------------------------------------------
// Kernel 1 (fused): split X / W strip sums (col+row) / tables
// ---------------------------------------------------------------------------
__global__ void __launch_bounds__(256) prep_kernel(const float* __restrict__ X,
                                                   const float* __restrict__ W,
                                                   const float* __restrict__ W1,
                                                   const float* __restrict__ b1) {
    __shared__ float rred[32][9];
    int b = blockIdx.x;
    int tid = threadIdx.x;
    if (b < 4096) {
        int gid = b * 256 + tid;
        int idx = gid * 4;
        float4 v = *(const float4*)(X + idx);
        __half hx = __float2half_rn(v.x), hy = __float2half_rn(v.y);
        __half hz = __float2half_rn(v.z), hw = __float2half_rn(v.w);
        __half lx = __float2half_rn(v.x - __half2float(hx));
        __half ly = __float2half_rn(v.y - __half2float(hy));
        __half lz = __float2half_rn(v.z - __half2float(hz));
        __half lw = __float2half_rn(v.w - __half2float(hw));
        uint32_t hi01 = (uint32_t)__half_as_ushort(hx) | ((uint32_t)__half_as_ushort(hy) << 16);
        uint32_t hi23 = (uint32_t)__half_as_ushort(hz) | ((uint32_t)__half_as_ushort(hw) << 16);
        uint32_t lo01 = (uint32_t)__half_as_ushort(lx) | ((uint32_t)__half_as_ushort(ly) << 16);
        uint32_t lo23 = (uint32_t)__half_as_ushort(lz) | ((uint32_t)__half_as_ushort(lw) << 16);
        *(uint2*)(g_Ahi + idx) = make_uint2(hi01, hi23);
        *(uint2*)(g_Alo + idx) = make_uint2(lo01, lo23);
    } else if (b < 4224) {
        int b2 = b - 4096;
        int rg = b2 >> 2;
        int cq = b2 & 3;
        int col = cq * 256 + tid;
        int r0  = rg * 32;
        int wl = tid & 31, wr = tid >> 5;
        float s = 0.f;
#pragma unroll
        for (int r = 0; r < 32; r++) {
            float w = W[(r0 + r) * N_U + col];
            s += w;
            float rs = w;
#pragma unroll
            for (int o = 16; o > 0; o >>= 1) rs += __shfl_xor_sync(0xffffffffu, rs, o);
            if (wl == 0) rred[r][wr] = rs;
        }
        g_colpart[rg][col] = s;
        __syncthreads();
        if (tid < 32) {
            float t = 0.f;
#pragma unroll
            for (int p = 0; p < 8; p++) t += rred[tid][p];
            g_rowpart[cq][r0 + tid] = t;
        }
    } else {
        int idx = (b - 4224) * 256 + tid;
        if (idx < N_U * H) {
            int i = idx / H, h = idx % H;
            float acc = 0.f;
#pragma unroll
            for (int t = 0; t < 10; t++) {
                float coef = W1[(3 + t) * H + h] + W1[(43 + t) * H + h]
                           - W1[(23 + t) * H + h] * INV1023;
                if ((i >> (9 - t)) & 1) acc += coef;
            }
            g_F[i][h] = acc;
        } else if (idx < 2 * N_U * H) {
            int r = idx - N_U * H;
            int j = r / H, h = r % H;
            float acc = b1[h];
#pragma unroll
            for (int s = 0; s < 10; s++) {
                float coef = W1[(13 + s) * H + h] + W1[(33 + s) * H + h]
                           - W1[(53 + s) * H + h] * INV1023;
                if ((j >> (9 - s)) & 1) acc += coef;
                acc += (512.f * INV1023) * (W1[(23 + s) * H + h] + W1[(53 + s) * H + h]);
            }
            g_G[j][h] = acc;
        } else if (idx < 2 * N_U * H + H) {
            int h = idx - 2 * N_U * H;
            g_ACR[0][h] = W1[h] - (W1[H + h] + W1[2 * H + h]) * INV1023;
            g_ACR[1][h] = W1[H + h] * INV1023;
            g_ACR[2][h] = W1[2 * H + h] * INV1023;
        }
    }
}

// ---------------------------------------------------------------------------
// Kernel 2: finish sums; build folded tables
// ---------------------------------------------------------------------------
__global__ void __launch_bounds__(256) fold_kernel() {
    int b = blockIdx.x;
    int tid = threadIdx.x;
    if (b < 4) {
        int col = b * 256 + tid;
        float s = 0.f;
#pragma unroll
        for (int p = 0; p < 32; p++) s += g_colpart[p][col];
#pragma unroll
        for (int q = 0; q < 3; q++) {
            float4 c = ((const float4*)g_ACR[1])[q];
            float4 g = ((const float4*)g_G[col])[q];
            float4 r;
            r.x = fmaf(c.x, s, g.x);
            r.y = fmaf(c.y, s, g.y);
            r.z = fmaf(c.z, s, g.z);
            r.w = fmaf(c.w, s, g.w);
            ((float4*)g_JG[col])[q] = r;
        }
    } else {
        int i = (b - 4) * 256 + tid;
        float s = g_rowpart[0][i] + g_rowpart[1][i] + g_rowpart[2][i] + g_rowpart[3][i];
#pragma unroll
        for (int q = 0; q < 3; q++) {
            float4 c = ((const float4*)g_ACR[2])[q];
            float4 f = ((const float4*)g_F[i])[q];
            float4 r;
            r.x = fmaf(c.x, s, f.x);
            r.y = fmaf(c.y, s, f.y);
            r.z = fmaf(c.z, s, f.z);
            r.w = fmaf(c.w, s, f.w);
            ((float4*)g_IF[i])[q] = r;
        }
    }
}

// ---------------------------------------------------------------------------
// Per-cell MLP -> fp16 hi/lo split of new_weight directly in [k][n]
// ---------------------------------------------------------------------------
__global__ void __launch_bounds__(256) mlp_kernel(const float* __restrict__ W,
                                                  const float* __restrict__ W2,
                                                  const float* __restrict__ b2,
                                                  const float* __restrict__ W3,
                                                  const float* __restrict__ b3) {
    __shared__ __align__(16) float sW2T[H][12];
    __shared__ __align__(16) float sA[12];
    __shared__ __align__(16) float sIF[12];
    __shared__ float sB2[H], sW3[H];
    __shared__ float sb3;
    int tid = threadIdx.x;
    int i = blockIdx.x;

    if (tid < 120) {
        int k = tid / 12, h = tid % 12;
        sW2T[k][h] = (h < H) ? W2[h * H + k] : 0.f;
    }
    if (tid >= 128 && tid < 140) sA[tid - 128]  = g_ACR[0][tid - 128];
    if (tid >= 160 && tid < 172) sIF[tid - 160] = g_IF[i][tid - 160];
    if (tid < H) { sB2[tid] = b2[tid]; sW3[tid] = W3[tid * 21]; }
    if (tid == 0) sb3 = b3[0];
    __syncthreads();

    float w[4];
#pragma unroll
    for (int c = 0; c < 4; c++) w[c] = W[i * N_U + c * 256 + tid];

    float z[4][12];
#pragma unroll
    for (int q = 0; q < 3; q++) {
        float4 a = ((const float4*)sA)[q];
        float4 f = ((const float4*)sIF)[q];
#pragma unroll
        for (int c = 0; c < 4; c++) {
            int j = c * 256 + tid;
            float4 g = ((const float4*)g_JG[j])[q];
            float tx = f.x + g.x, ty = f.y + g.y, tz = f.z + g.z, tw = f.w + g.w;
            z[c][q * 4 + 0] = fmaxf(fmaf(a.x, w[c], tx), 0.f);
            z[c][q * 4 + 1] = fmaxf(fmaf(a.y, w[c], ty), 0.f);
            z[c][q * 4 + 2] = fmaxf(fmaf(a.z, w[c], tz), 0.f);
            z[c][q * 4 + 3] = fmaxf(fmaf(a.w, w[c], tw), 0.f);
        }
    }

    float upd[4] = {sb3, sb3, sb3, sb3};
#pragma unroll
    for (int k = 0; k < H; k++) {
        const float4* w4 = (const float4*)sW2T[k];
        float4 wa = w4[0], wb = w4[1];
        float2 wc = *(const float2*)&sW2T[k][8];
        float bk = sB2[k], w3k = sW3[k];
#pragma unroll
        for (int c = 0; c < 4; c++) {
            float y = bk;
            y = fmaf(z[c][0], wa.x, y);
            y = fmaf(z[c][1], wa.y, y);
            y = fmaf(z[c][2], wa.z, y);
            y = fmaf(z[c][3], wa.w, y);
            y = fmaf(z[c][4], wb.x, y);
            y = fmaf(z[c][5], wb.y, y);
            y = fmaf(z[c][6], wb.z, y);
            y = fmaf(z[c][7], wb.w, y);
            y = fmaf(z[c][8], wc.x, y);
            y = fmaf(z[c][9], wc.y, y);
            upd[c] = fmaf(fmaxf(y, 0.f), w3k, upd[c]);
        }
    }
#pragma unroll
    for (int c = 0; c < 4; c++) {
        int j = c * 256 + tid;
        float v = w[c] + upd[c];
        __half h = __float2half_rn(v);
        __half l = __float2half_rn(v - __half2float(h));
        g_Bh[(size_t)i * N_U + j] = __half_as_ushort(h);
        g_Bl[(size_t)i * N_U + j] = __half_as_ushort(l);
    }
}

// ---------------------------------------------------------------------------
// GEMM fused 3-pass: per k-chunk load Ahi/Alo/Bh/Bl ONCE, do 3 MMA groups.
// out = relu( Ahi*Bh + Ahi*Bl + Alo*Bh ), 512 threads / 16 warps.
// BM=112, BN=256, 32 super-iters over K. 3-stage cp.async pipeline.
// cp.async per iter: 2944 chunks (was 3x1472 over equivalent work = -33%).
// ---------------------------------------------------------------------------
#define BM 112
#define BN 256
#define BK 32
#define STAGES 3
#define AROW 40
#define BROW 528
#define AHB (BM * AROW * 2)               // 8960
#define BHB (BK * BROW)                   // 16896
#define OFF_ALO  AHB                      // 8960
#define OFF_BH   (2 * AHB)                // 17920
#define OFF_BL   (2 * AHB + BHB)          // 34816
#define STBYTES  (2 * AHB + 2 * BHB)      // 51712
#define SMEM_GEMM (STAGES * STBYTES)      // 155136
#define ITERS 32

__device__ __forceinline__ void gemm_load_stage(uint32_t sb, int tid, int mt, int nt,
                                                int it, int st) {
    int k0  = it * BK;
    uint32_t base = sb + st * STBYTES;
    if (tid < BM * 4) {                               // A hi+lo: 448 chunks each
        int row = tid >> 2;
        int off = (tid & 3) * 8;
        int grow = mt * BM + row;
        if (grow > 4095) grow = 4095;
        CP_ASYNC16(base + row * (AROW * 2) + off * 2,
                   (const char*)(g_Ahi + (size_t)grow * N_U + k0 + off));
        CP_ASYNC16(base + OFF_ALO + row * (AROW * 2) + off * 2,
                   (const char*)(g_Alo + (size_t)grow * N_U + k0 + off));
    }
#pragma unroll
    for (int q = 0; q < 2; q++) {                     // B hi+lo: 1024 chunks each
        int chunk = tid + q * 512;
        int krow = chunk >> 5;
        int off  = (chunk & 31) * 16;
        CP_ASYNC16(base + OFF_BH + krow * BROW + off,
                   (const char*)(g_Bh + (size_t)(k0 + krow) * N_U + nt * BN) + off);
        CP_ASYNC16(base + OFF_BL + krow * BROW + off,
                   (const char*)(g_Bl + (size_t)(k0 + krow) * N_U + nt * BN) + off);
    }
}

template <int FR, int FBASE>
__device__ __forceinline__ void gemm_main(uint32_t sb, int tid, int lane, int nw,
                                          int mt, int nt, float* __restrict__ out) {
    float c[FR][4][4];
#pragma unroll
    for (int f = 0; f < FR; f++)
#pragma unroll
        for (int n = 0; n < 4; n++)
#pragma unroll
            for (int q = 0; q < 4; q++) c[f][n][q] = 0.f;

    int lrow = lane & 15;
    int lcol = (lane >> 4) * 16;

    for (int i = 0; i < ITERS; i++) {
        CP_WAIT(1);
        __syncthreads();

        int nx = i + STAGES - 1;
        if (nx < ITERS) gemm_load_stage(sb, tid, mt, nt, nx, nx % STAGES);
        CP_COMMIT();

        uint32_t base = sb + (i % STAGES) * STBYTES;

#pragma unroll
        for (int ks = 0; ks < 2; ks++) {
            // group 1: a_hi x b_h
            uint32_t ah[FR][4];
#pragma unroll
            for (int f = 0; f < FR; f++)
                LDMATRIX_X4(ah[f][0], ah[f][1], ah[f][2], ah[f][3],
                    base + ((FBASE + f) * 16 + lrow) * (AROW * 2) + ks * 32 + lcol);
            uint32_t bh[4][2];
#pragma unroll
            for (int g = 0; g < 2; g++) {
                uint32_t r0, r1, r2, r3;
                LDMATRIX_X4_T(r0, r1, r2, r3,
                    base + OFF_BH + (ks * 16 + lrow) * BROW + nw * 64 + g * 32 + lcol);
                bh[2 * g][0] = r0;  bh[2 * g][1] = r1;
                bh[2 * g + 1][0] = r2;  bh[2 * g + 1][1] = r3;
            }
#pragma unroll
            for (int f = 0; f < FR; f++)
#pragma unroll
                for (int n = 0; n < 4; n++)
                    MMA_F16F32(c[f][n][0], c[f][n][1], c[f][n][2], c[f][n][3],
                               ah[f][0], ah[f][1], ah[f][2], ah[f][3], bh[n][0], bh[n][1]);
            // group 2: a_hi x b_l
            uint32_t bl[4][2];
#pragma unroll
            for (int g = 0; g < 2; g++) {
                uint32_t r0, r1, r2, r3;
                LDMATRIX_X4_T(r0, r1, r2, r3,
                    base + OFF_BL + (ks * 16 + lrow) * BROW + nw * 64 + g * 32 + lcol);
                bl[2 * g][0] = r0;  bl[2 * g][1] = r1;
                bl[2 * g + 1][0] = r2;  bl[2 * g + 1][1] = r3;
            }
#pragma unroll
            for (int f = 0; f < FR; f++)
#pragma unroll
                for (int n = 0; n < 4; n++)
                    MMA_F16F32(c[f][n][0], c[f][n][1], c[f][n][2], c[f][n][3],
                               ah[f][0], ah[f][1], ah[f][2], ah[f][3], bl[n][0], bl[n][1]);
            // group 3: a_lo x b_h (a_hi registers recycled)
            uint32_t al[FR][4];
#pragma unroll
            for (int f = 0; f < FR; f++)
                LDMATRIX_X4(al[f][0], al[f][1], al[f][2], al[f][3],
                    base + OFF_ALO + ((FBASE + f) * 16 + lrow) * (AROW * 2) + ks * 32 + lcol);
#pragma unroll
            for (int f = 0; f < FR; f++)
#pragma unroll
                for (int n = 0; n < 4; n++)
                    MMA_F16F32(c[f][n][0], c[f][n][1], c[f][n][2], c[f][n][3],
                               al[f][0], al[f][1], al[f][2], al[f][3], bh[n][0], bh[n][1]);
        }
    }

    // Epilogue: relu + guarded store
    int cbase = nt * BN + nw * 32 + (lane & 3) * 2;
#pragma unroll
    for (int f = 0; f < FR; f++) {
        int r = mt * BM + (FBASE + f) * 16 + (lane >> 2);
#pragma unroll
        for (int n = 0; n < 4; n++) {
            int cc = cbase + n * 8;
            if (r < BATCH) {
                float2 v0;
                v0.x = fmaxf(c[f][n][0], 0.f);
                v0.y = fmaxf(c[f][n][1], 0.f);
                *(float2*)(out + (size_t)r * N_U + cc) = v0;
            }
            if (r + 8 < BATCH) {
                float2 v1;
                v1.x = fmaxf(c[f][n][2], 0.f);
                v1.y = fmaxf(c[f][n][3], 0.f);
                *(float2*)(out + (size_t)(r + 8) * N_U + cc) = v1;
            }
        }
    }
}

__global__ void __launch_bounds__(512, 1) gemm_mma_kernel(float* __restrict__ out) {
    extern __shared__ char smem[];
    uint32_t sb = smem_u32(smem);
    int tid  = threadIdx.x;
    int wid  = tid >> 5;
    int lane = tid & 31;

    int mt = blockIdx.x % 37;
    int nt = blockIdx.x / 37;
    int nw = wid & 7;

#pragma unroll
    for (int s = 0; s < STAGES - 1; s++) {
        gemm_load_stage(sb, tid, mt, nt, s, s);
        CP_COMMIT();
    }

    if (wid < 8) gemm_main<4, 0>(sb, tid, lane, nw, mt, nt, out);
    else         gemm_main<3, 4>(sb, tid, lane, nw, mt, nt, out);
}

// ---------------------------------------------------------------------------
// Row softmax in-place
// ---------------------------------------------------------------------------
__global__ void __launch_bounds__(256) softmax_kernel(float* __restrict__ out) {
    __shared__ float redm[8];
    __shared__ float reds[8];
    __shared__ float bval[2];
    int row = blockIdx.x, tid = threadIdx.x;
    int lane = tid & 31, wid = tid >> 5;

    float4 v = *(float4*)(out + row * N_U + tid * 4);
    float m = fmaxf(fmaxf(v.x, v.y), fmaxf(v.z, v.w));
#pragma unroll
    for (int o = 16; o > 0; o >>= 1) m = fmaxf(m, __shfl_xor_sync(0xffffffffu, m, o));
    if (lane == 0) redm[wid] = m;
    __syncthreads();
    if (tid == 0) {
        float t = redm[0];
#pragma unroll
        for (int i = 1; i < 8; i++) t = fmaxf(t, redm[i]);
        bval[0] = t;
    }
    __syncthreads();
    m = bval[0];
    v.x = __expf(v.x - m); v.y = __expf(v.y - m);
    v.z = __expf(v.z - m); v.w = __expf(v.w - m);
    float s = v.x + v.y + v.z + v.w;
#pragma unroll
    for (int o = 16; o > 0; o >>= 1) s += __shfl_xor_sync(0xffffffffu, s, o);
    if (lane == 0) reds[wid] = s;
    __syncthreads();
    if (tid == 0) {
        float t = 0.f;
#pragma unroll
        for (int i = 0; i < 8; i++) t += reds[i];
        bval[1] = 1.f / t;
    }
    __syncthreads();
    float inv = bval[1];
    v.x *= inv; v.y *= inv; v.z *= inv; v.w *= inv;
    *(float4*)(out + row * N_U + tid * 4) = v;
}

// ---------------------------------------------------------------------------
// Entry point
// ---------------------------------------------------------------------------
extern "C" void kernel_launch(void* const* d_in, const int* in_sizes, int n_in,
                              void* d_out, int out_size) {
    const float* X      = (const float*)d_in[0];
    const float* weight = (const float*)d_in[1];
    const float* W1     = (const float*)d_in[3];
    const float* b1     = (const float*)d_in[4];
    const float* W2     = (const float*)d_in[5];
    const float* b2     = (const float*)d_in[6];
    const float* W3     = (const float*)d_in[7];
    const float* b3     = (const float*)d_in[8];
    float* out = (float*)d_out;

    static bool attr_done = false;
    if (!attr_done) {
        cudaFuncSetAttribute(gemm_mma_kernel,
                             cudaFuncAttributeMaxDynamicSharedMemorySize, SMEM_GEMM);
        attr_done = true;
    }

    prep_kernel<<<4305, 256>>>(X, weight, W1, b1);                      // 1
    fold_kernel<<<8, 256>>>();                                          // 2
    mlp_kernel<<<N_U, 256>>>(weight, W2, b2, W3, b3);                   // 3
    gemm_mma_kernel<<<148, 512, SMEM_GEMM>>>(out);                      // 4
    softmax_kernel<<<BATCH, 256>>>(out);                                // 5
}

// round 15
// speedup vs baseline: 2.5053x; 1.1816x over previous
#include <cuda_runtime.h>
#include <cuda.h>
#include <cuda_fp16.h>
#include <cstdint>

// Problem constants
#define N_U   1024
#define BATCH 4096
#define H     10
#define INV1023 (1.0f / 1023.0f)

// ---------------------------------------------------------------------------
// Scratch (device globals)
// ---------------------------------------------------------------------------
__device__ float g_colpart[32][N_U];
__device__ float g_rowpart[4][N_U];
__device__ __align__(16) float g_F[N_U][12];
__device__ __align__(16) float g_G[N_U][12];
__device__ __align__(16) float g_IF[N_U][12];
__device__ __align__(16) float g_JG[N_U][12];
__device__ __align__(16) float g_ACR[3][12];

// fp16 split operands. A: [m][k]. B: [k][n]
__device__ __align__(256) unsigned short g_Ahi[BATCH * N_U];
__device__ __align__(256) unsigned short g_Alo[BATCH * N_U];
__device__ __align__(256) unsigned short g_Bh[N_U * N_U];
__device__ __align__(256) unsigned short g_Bl[N_U * N_U];

// ---------------------------------------------------------------------------
// Helpers
// ---------------------------------------------------------------------------
__device__ __forceinline__ uint32_t smem_u32(const void* p) {
    uint32_t a;
    asm("{ .reg .u64 t; cvta.to.shared.u64 t, %1; cvt.u32.u64 %0, t; }" : "=r"(a) : "l"(p));
    return a;
}

#define SWZ(o) ((o) ^ (((o) >> 3) & 0x70))

#define LDMATRIX_X4(r0, r1, r2, r3, addr) \
    asm volatile("ldmatrix.sync.aligned.m8n8.x4.shared.b16 {%0,%1,%2,%3}, [%4];" \
        : "=r"(r0), "=r"(r1), "=r"(r2), "=r"(r3) : "r"(addr))

#define LDMATRIX_X4_T(r0, r1, r2, r3, addr) \
    asm volatile("ldmatrix.sync.aligned.m8n8.x4.trans.shared.b16 {%0,%1,%2,%3}, [%4];" \
        : "=r"(r0), "=r"(r1), "=r"(r2), "=r"(r3) : "r"(addr))

#define MMA_F16F32(c0, c1, c2, c3, a0, a1, a2, a3, b0, b1) \
    asm volatile("mma.sync.aligned.m16n8k16.row.col.f32.f16.f16.f32 " \
        "{%0,%1,%2,%3}, {%4,%5,%6,%7}, {%8,%9}, {%0,%1,%2,%3};" \
        : "+f"(c0), "+f"(c1), "+f"(c2), "+f"(c3) \
        : "r"(a0), "r"(a1), "r"(a2), "r"(a3), "r"(b0), "r"(b1))

#define MBARRIER_INIT(a, n) \
    asm volatile("mbarrier.init.shared.b64 [%0], %1;" :: "r"(a), "r"(n) : "memory")
#define MBARRIER_EXPECT_TX(a, bytes) \
    asm volatile("mbarrier.arrive.expect_tx.shared.b64 _, [%0], %1;" \
                 :: "r"(a), "r"(bytes) : "memory")
#define MBARRIER_WAIT_PARITY(a, par) do {                                          \
    uint32_t _m = (a); uint32_t _p = (par); uint32_t _d;                            \
    asm volatile("{\n\t.reg .pred p;\n\t"                                           \
        "mbarrier.try_wait.parity.acquire.cta.shared::cta.b64 p, [%1], %2;\n\t"     \
        "selp.b32 %0, 1, 0, p;\n\t}" : "=r"(_d) : "r"(_m), "r"(_p) : "memory");     \
    if (!_d) {                                                                      \
        asm volatile("{\n\t.reg .pred P1;\n\t"                                      \
            "WL_%=:\n\t"                                                            \
            "mbarrier.try_wait.parity.acquire.cta.shared::cta.b64 P1, [%0], %1, 0x989680;\n\t" \
            "@P1 bra.uni WD_%=;\n\t bra.uni WL_%=;\n\t WD_%=:\n\t}"                 \
            :: "r"(_m), "r"(_p) : "memory");                                        \
    }                                                                               \
} while (0)

#define TMA2D(smem, map, c0, c1, mbar) \
    asm volatile("cp.async.bulk.tensor.2d.shared::cta.global.tile.mbarrier::complete_tx::bytes " \
        "[%0], [%1, {%2, %3}], [%4];" \
        :: "r"(smem), "l"(map), "r"(c0), "r"(c1), "r"(mbar) : "memory")

// ---------------------------------------------------------------------------
// Kernel 1 (fused): split X / W strip sums (col+row) / tables
// ---------------------------------------------------------------------------
__global__ void __launch_bounds__(256) prep_kernel(const float* __restrict__ X,
                                                   const float* __restrict__ W,
                                                   const float* __restrict__ W1,
                                                   const float* __restrict__ b1) {
    __shared__ float rred[32][9];
    int b = blockIdx.x;
    int tid = threadIdx.x;
    if (b < 4096) {
        int gid = b * 256 + tid;
        int idx = gid * 4;
        float4 v = *(const float4*)(X + idx);
        __half hx = __float2half_rn(v.x), hy = __float2half_rn(v.y);
        __half hz = __float2half_rn(v.z), hw = __float2half_rn(v.w);
        __half lx = __float2half_rn(v.x - __half2float(hx));
        __half ly = __float2half_rn(v.y - __half2float(hy));
        __half lz = __float2half_rn(v.z - __half2float(hz));
        __half lw = __float2half_rn(v.w - __half2float(hw));
        uint32_t hi01 = (uint32_t)__half_as_ushort(hx) | ((uint32_t)__half_as_ushort(hy) << 16);
        uint32_t hi23 = (uint32_t)__half_as_ushort(hz) | ((uint32_t)__half_as_ushort(hw) << 16);
        uint32_t lo01 = (uint32_t)__half_as_ushort(lx) | ((uint32_t)__half_as_ushort(ly) << 16);
        uint32_t lo23 = (uint32_t)__half_as_ushort(lz) | ((uint32_t)__half_as_ushort(lw) << 16);
        *(uint2*)(g_Ahi + idx) = make_uint2(hi01, hi23);
        *(uint2*)(g_Alo + idx) = make_uint2(lo01, lo23);
    } else if (b < 4224) {
        int b2 = b - 4096;
        int rg = b2 >> 2;
        int cq = b2 & 3;
        int col = cq * 256 + tid;
        int r0  = rg * 32;
        int wl = tid & 31, wr = tid >> 5;
        float s = 0.f;
#pragma unroll
        for (int r = 0; r < 32; r++) {
            float w = W[(r0 + r) * N_U + col];
            s += w;
            float rs = w;
#pragma unroll
            for (int o = 16; o > 0; o >>= 1) rs += __shfl_xor_sync(0xffffffffu, rs, o);
            if (wl == 0) rred[r][wr] = rs;
        }
        g_colpart[rg][col] = s;
        __syncthreads();
        if (tid < 32) {
            float t = 0.f;
#pragma unroll
            for (int p = 0; p < 8; p++) t += rred[tid][p];
            g_rowpart[cq][r0 + tid] = t;
        }
    } else {
        int idx = (b - 4224) * 256 + tid;
        if (idx < N_U * H) {
            int i = idx / H, h = idx % H;
            float acc = 0.f;
#pragma unroll
            for (int t = 0; t < 10; t++) {
                float coef = W1[(3 + t) * H + h] + W1[(43 + t) * H + h]
                           - W1[(23 + t) * H + h] * INV1023;
                if ((i >> (9 - t)) & 1) acc += coef;
            }
            g_F[i][h] = acc;
        } else if (idx < 2 * N_U * H) {
            int r = idx - N_U * H;
            int j = r / H, h = r % H;
            float acc = b1[h];
#pragma unroll
            for (int s = 0; s < 10; s++) {
                float coef = W1[(13 + s) * H + h] + W1[(33 + s) * H + h]
                           - W1[(53 + s) * H + h] * INV1023;
                if ((j >> (9 - s)) & 1) acc += coef;
                acc += (512.f * INV1023) * (W1[(23 + s) * H + h] + W1[(53 + s) * H + h]);
            }
            g_G[j][h] = acc;
        } else if (idx < 2 * N_U * H + H) {
            int h = idx - 2 * N_U * H;
            g_ACR[0][h] = W1[h] - (W1[H + h] + W1[2 * H + h]) * INV1023;
            g_ACR[1][h] = W1[H + h] * INV1023;
            g_ACR[2][h] = W1[2 * H + h] * INV1023;
        }
    }
}

// ---------------------------------------------------------------------------
// Kernel 2: finish sums; build folded tables
// ---------------------------------------------------------------------------
__global__ void __launch_bounds__(256) fold_kernel() {
    int b = blockIdx.x;
    int tid = threadIdx.x;
    if (b < 4) {
        int col = b * 256 + tid;
        float s = 0.f;
#pragma unroll
        for (int p = 0; p < 32; p++) s += g_colpart[p][col];
#pragma unroll
        for (int q = 0; q < 3; q++) {
            float4 c = ((const float4*)g_ACR[1])[q];
            float4 g = ((const float4*)g_G[col])[q];
            float4 r;
            r.x = fmaf(c.x, s, g.x);
            r.y = fmaf(c.y, s, g.y);
            r.z = fmaf(c.z, s, g.z);
            r.w = fmaf(c.w, s, g.w);
            ((float4*)g_JG[col])[q] = r;
        }
    } else {
        int i = (b - 4) * 256 + tid;
        float s = g_rowpart[0][i] + g_rowpart[1][i] + g_rowpart[2][i] + g_rowpart[3][i];
#pragma unroll
        for (int q = 0; q < 3; q++) {
            float4 c = ((const float4*)g_ACR[2])[q];
            float4 f = ((const float4*)g_F[i])[q];
            float4 r;
            r.x = fmaf(c.x, s, f.x);
            r.y = fmaf(c.y, s, f.y);
            r.z = fmaf(c.z, s, f.z);
            r.w = fmaf(c.w, s, f.w);
            ((float4*)g_IF[i])[q] = r;
        }
    }
}

// ---------------------------------------------------------------------------
// Per-cell MLP -> fp16 hi/lo split of new_weight directly in [k][n]
// ---------------------------------------------------------------------------
__global__ void __launch_bounds__(256) mlp_kernel(const float* __restrict__ W,
                                                  const float* __restrict__ W2,
                                                  const float* __restrict__ b2,
                                                  const float* __restrict__ W3,
                                                  const float* __restrict__ b3) {
    __shared__ __align__(16) float sW2T[H][12];
    __shared__ __align__(16) float sA[12];
    __shared__ __align__(16) float sIF[12];
    __shared__ float sB2[H], sW3[H];
    __shared__ float sb3;
    int tid = threadIdx.x;
    int i = blockIdx.x;

    if (tid < 120) {
        int k = tid / 12, h = tid % 12;
        sW2T[k][h] = (h < H) ? W2[h * H + k] : 0.f;
    }
    if (tid >= 128 && tid < 140) sA[tid - 128]  = g_ACR[0][tid - 128];
    if (tid >= 160 && tid < 172) sIF[tid - 160] = g_IF[i][tid - 160];
    if (tid < H) { sB2[tid] = b2[tid]; sW3[tid] = W3[tid * 21]; }
    if (tid == 0) sb3 = b3[0];
    __syncthreads();

    float w[4];
#pragma unroll
    for (int c = 0; c < 4; c++) w[c] = W[i * N_U + c * 256 + tid];

    float z[4][12];
#pragma unroll
    for (int q = 0; q < 3; q++) {
        float4 a = ((const float4*)sA)[q];
        float4 f = ((const float4*)sIF)[q];
#pragma unroll
        for (int c = 0; c < 4; c++) {
            int j = c * 256 + tid;
            float4 g = ((const float4*)g_JG[j])[q];
            float tx = f.x + g.x, ty = f.y + g.y, tz = f.z + g.z, tw = f.w + g.w;
            z[c][q * 4 + 0] = fmaxf(fmaf(a.x, w[c], tx), 0.f);
            z[c][q * 4 + 1] = fmaxf(fmaf(a.y, w[c], ty), 0.f);
            z[c][q * 4 + 2] = fmaxf(fmaf(a.z, w[c], tz), 0.f);
            z[c][q * 4 + 3] = fmaxf(fmaf(a.w, w[c], tw), 0.f);
        }
    }

    float upd[4] = {sb3, sb3, sb3, sb3};
#pragma unroll
    for (int k = 0; k < H; k++) {
        const float4* w4 = (const float4*)sW2T[k];
        float4 wa = w4[0], wb = w4[1];
        float2 wc = *(const float2*)&sW2T[k][8];
        float bk = sB2[k], w3k = sW3[k];
#pragma unroll
        for (int c = 0; c < 4; c++) {
            float y = bk;
            y = fmaf(z[c][0], wa.x, y);
            y = fmaf(z[c][1], wa.y, y);
            y = fmaf(z[c][2], wa.z, y);
            y = fmaf(z[c][3], wa.w, y);
            y = fmaf(z[c][4], wb.x, y);
            y = fmaf(z[c][5], wb.y, y);
            y = fmaf(z[c][6], wb.z, y);
            y = fmaf(z[c][7], wb.w, y);
            y = fmaf(z[c][8], wc.x, y);
            y = fmaf(z[c][9], wc.y, y);
            upd[c] = fmaf(fmaxf(y, 0.f), w3k, upd[c]);
        }
    }
#pragma unroll
    for (int c = 0; c < 4; c++) {
        int j = c * 256 + tid;
        float v = w[c] + upd[c];
        __half h = __float2half_rn(v);
        __half l = __float2half_rn(v - __half2float(h));
        g_Bh[(size_t)i * N_U + j] = __half_as_ushort(h);
        g_Bl[(size_t)i * N_U + j] = __half_as_ushort(l);
    }
}

// ---------------------------------------------------------------------------
// TMA GEMM: out = relu( Ahi*Bh + Ahi*Bl + Alo*Bh ), 512 thr / 16 warps.
// BM=112, BN=256, BK=64, 16 super-iters, 2-stage mbarrier TMA pipeline.
// Per stage: Ahi(112x64) + Alo + Bh(4 boxes 64x64) + Bl = 94208 bytes, 10 TMAs.
// SW128 swizzle throughout; ldmatrix addresses use SWZ().
// ---------------------------------------------------------------------------
#define BM 112
#define BN 256
#define GITERS 16
#define A_SZ   (112 * 128)                 // 14336
#define BOX_SZ (64 * 128)                  // 8192
#define OFF_ALO  A_SZ                      // 14336
#define OFF_BH   (2 * A_SZ)                // 28672
#define OFF_BL   (2 * A_SZ + 4 * BOX_SZ)   // 61440
#define STAGEB   (2 * A_SZ + 8 * BOX_SZ)   // 94208
#define SMEM_GEMM (1024 + 2 * STAGEB)      // 189440

__device__ __forceinline__ void tma_issue_stage(uint32_t sb, int st, int it,
                                                int mt, int nt,
                                                const CUtensorMap* tAhi,
                                                const CUtensorMap* tAlo,
                                                const CUtensorMap* tBh,
                                                const CUtensorMap* tBl) {
    uint32_t base = sb + 1024 + st * STAGEB;
    uint32_t mb   = sb + st * 8;
    MBARRIER_EXPECT_TX(mb, (uint32_t)STAGEB);
    int k0 = it * 64;
    int m0 = mt * BM;
    TMA2D(base,           tAhi, k0, m0, mb);
    TMA2D(base + OFF_ALO, tAlo, k0, m0, mb);
#pragma unroll
    for (int bx = 0; bx < 4; bx++) {
        int n0 = nt * BN + bx * 64;
        TMA2D(base + OFF_BH + bx * BOX_SZ, tBh, n0, k0, mb);
        TMA2D(base + OFF_BL + bx * BOX_SZ, tBl, n0, k0, mb);
    }
}

template <int FR, int FBASE>
__device__ __forceinline__ void gemm_main(uint32_t sb, int tid, int lane, int nw,
                                          int mt, int nt,
                                          const CUtensorMap* tAhi, const CUtensorMap* tAlo,
                                          const CUtensorMap* tBh,  const CUtensorMap* tBl,
                                          float* __restrict__ out) {
    float c[FR][4][4];
#pragma unroll
    for (int f = 0; f < FR; f++)
#pragma unroll
        for (int n = 0; n < 4; n++)
#pragma unroll
            for (int q = 0; q < 4; q++) c[f][n][q] = 0.f;

    int lrow = lane & 15;
    int lcol = (lane >> 4) * 16;
    int ph[2] = {0, 0};

    for (int i = 0; i < GITERS; i++) {
        int st = i & 1;
        MBARRIER_WAIT_PARITY(sb + st * 8, ph[st]);
        ph[st] ^= 1;

        uint32_t base = sb + 1024 + st * STAGEB;
        uint32_t bboxH = base + OFF_BH + (nw >> 1) * BOX_SZ;
        uint32_t bboxL = base + OFF_BL + (nw >> 1) * BOX_SZ;
        int bnn = (nw & 1) * 64;

#pragma unroll
        for (int ks = 0; ks < 4; ks++) {
            // group 1: a_hi x b_h
            uint32_t ah[FR][4];
#pragma unroll
            for (int f = 0; f < FR; f++) {
                uint32_t off = ((FBASE + f) * 16 + lrow) * 128 + ks * 32 + lcol;
                LDMATRIX_X4(ah[f][0], ah[f][1], ah[f][2], ah[f][3], base + SWZ(off));
            }
            uint32_t bh[4][2];
#pragma unroll
            for (int g = 0; g < 2; g++) {
                uint32_t r0, r1, r2, r3;
                uint32_t off = (ks * 16 + lrow) * 128 + bnn + g * 32 + lcol;
                LDMATRIX_X4_T(r0, r1, r2, r3, bboxH + SWZ(off));
                bh[2 * g][0] = r0;  bh[2 * g][1] = r1;
                bh[2 * g + 1][0] = r2;  bh[2 * g + 1][1] = r3;
            }
#pragma unroll
            for (int f = 0; f < FR; f++)
#pragma unroll
                for (int n = 0; n < 4; n++)
                    MMA_F16F32(c[f][n][0], c[f][n][1], c[f][n][2], c[f][n][3],
                               ah[f][0], ah[f][1], ah[f][2], ah[f][3], bh[n][0], bh[n][1]);
            // group 2: a_hi x b_l
            uint32_t bl[4][2];
#pragma unroll
            for (int g = 0; g < 2; g++) {
                uint32_t r0, r1, r2, r3;
                uint32_t off = (ks * 16 + lrow) * 128 + bnn + g * 32 + lcol;
                LDMATRIX_X4_T(r0, r1, r2, r3, bboxL + SWZ(off));
                bl[2 * g][0] = r0;  bl[2 * g][1] = r1;
                bl[2 * g + 1][0] = r2;  bl[2 * g + 1][1] = r3;
            }
#pragma unroll
            for (int f = 0; f < FR; f++)
#pragma unroll
                for (int n = 0; n < 4; n++)
                    MMA_F16F32(c[f][n][0], c[f][n][1], c[f][n][2], c[f][n][3],
                               ah[f][0], ah[f][1], ah[f][2], ah[f][3], bl[n][0], bl[n][1]);
            // group 3: a_lo x b_h
            uint32_t al[FR][4];
#pragma unroll
            for (int f = 0; f < FR; f++) {
                uint32_t off = ((FBASE + f) * 16 + lrow) * 128 + ks * 32 + lcol;
                LDMATRIX_X4(al[f][0], al[f][1], al[f][2], al[f][3],
                            base + OFF_ALO + SWZ(off));
            }
#pragma unroll
            for (int f = 0; f < FR; f++)
#pragma unroll
                for (int n = 0; n < 4; n++)
                    MMA_F16F32(c[f][n][0], c[f][n][1], c[f][n][2], c[f][n][3],
                               al[f][0], al[f][1], al[f][2], al[f][3], bh[n][0], bh[n][1]);
        }

        __syncthreads();                          // all warps done reading stage
        if (tid == 0 && i + 2 < GITERS)
            tma_issue_stage(sb, st, i + 2, mt, nt, tAhi, tAlo, tBh, tBl);
    }

    // Epilogue: relu + guarded store
    int cbase = nt * BN + nw * 32 + (lane & 3) * 2;
#pragma unroll
    for (int f = 0; f < FR; f++) {
        int r = mt * BM + (FBASE + f) * 16 + (lane >> 2);
#pragma unroll
        for (int n = 0; n < 4; n++) {
            int cc = cbase + n * 8;
            if (r < BATCH) {
                float2 v0;
                v0.x = fmaxf(c[f][n][0], 0.f);
                v0.y = fmaxf(c[f][n][1], 0.f);
                *(float2*)(out + (size_t)r * N_U + cc) = v0;
            }
            if (r + 8 < BATCH) {
                float2 v1;
                v1.x = fmaxf(c[f][n][2], 0.f);
                v1.y = fmaxf(c[f][n][3], 0.f);
                *(float2*)(out + (size_t)(r + 8) * N_U + cc) = v1;
            }
        }
    }
}

__global__ void __launch_bounds__(512, 1)
gemm_tma_kernel(const __grid_constant__ CUtensorMap tAhi,
                const __grid_constant__ CUtensorMap tAlo,
                const __grid_constant__ CUtensorMap tBh,
                const __grid_constant__ CUtensorMap tBl,
                float* __restrict__ out) {
    extern __shared__ __align__(1024) char smem[];
    uint32_t sb = smem_u32(smem);
    int tid  = threadIdx.x;
    int wid  = tid >> 5;
    int lane = tid & 31;

    int mt = blockIdx.x % 37;
    int nt = blockIdx.x / 37;
    int nw = wid & 7;

    if (tid == 0) {
        MBARRIER_INIT(sb + 0, 1);
        MBARRIER_INIT(sb + 8, 1);
    }
    __syncthreads();
    if (tid == 0) {
        tma_issue_stage(sb, 0, 0, mt, nt, &tAhi, &tAlo, &tBh, &tBl);
        tma_issue_stage(sb, 1, 1, mt, nt, &tAhi, &tAlo, &tBh, &tBl);
    }

    if (wid < 8) gemm_main<4, 0>(sb, tid, lane, nw, mt, nt, &tAhi, &tAlo, &tBh, &tBl, out);
    else         gemm_main<3, 4>(sb, tid, lane, nw, mt, nt, &tAhi, &tAlo, &tBh, &tBl, out);
}

// ---------------------------------------------------------------------------
// Row softmax in-place
// ---------------------------------------------------------------------------
__global__ void __launch_bounds__(256) softmax_kernel(float* __restrict__ out) {
    __shared__ float redm[8];
    __shared__ float reds[8];
    __shared__ float bval[2];
    int row = blockIdx.x, tid = threadIdx.x;
    int lane = tid & 31, wid = tid >> 5;

    float4 v = *(float4*)(out + row * N_U + tid * 4);
    float m = fmaxf(fmaxf(v.x, v.y), fmaxf(v.z, v.w));
#pragma unroll
    for (int o = 16; o > 0; o >>= 1) m = fmaxf(m, __shfl_xor_sync(0xffffffffu, m, o));
    if (lane == 0) redm[wid] = m;
    __syncthreads();
    if (tid == 0) {
        float t = redm[0];
#pragma unroll
        for (int i = 1; i < 8; i++) t = fmaxf(t, redm[i]);
        bval[0] = t;
    }
    __syncthreads();
    m = bval[0];
    v.x = __expf(v.x - m); v.y = __expf(v.y - m);
    v.z = __expf(v.z - m); v.w = __expf(v.w - m);
    float s = v.x + v.y + v.z + v.w;
#pragma unroll
    for (int o = 16; o > 0; o >>= 1) s += __shfl_xor_sync(0xffffffffu, s, o);
    if (lane == 0) reds[wid] = s;
    __syncthreads();
    if (tid == 0) {
        float t = 0.f;
#pragma unroll
        for (int i = 0; i < 8; i++) t += reds[i];
        bval[1] = 1.f / t;
    }
    __syncthreads();
    float inv = bval[1];
    v.x *= inv; v.y *= inv; v.z *= inv; v.w *= inv;
    *(float4*)(out + row * N_U + tid * 4) = v;
}

// ---------------------------------------------------------------------------
// Entry point. Tensormaps built once via driver entry point (no -lcuda needed).
// ---------------------------------------------------------------------------
typedef CUresult (*tme_fn)(CUtensorMap*, CUtensorMapDataType, cuuint32_t, void*,
                           const cuuint64_t*, const cuuint64_t*, const cuuint32_t*,
                           const cuuint32_t*, CUtensorMapInterleave, CUtensorMapSwizzle,
                           CUtensorMapL2promotion, CUtensorMapFloatOOBfill);

extern "C" void kernel_launch(void* const* d_in, const int* in_sizes, int n_in,
                              void* d_out, int out_size) {
    const float* X      = (const float*)d_in[0];
    const float* weight = (const float*)d_in[1];
    const float* W1     = (const float*)d_in[3];
    const float* b1     = (const float*)d_in[4];
    const float* W2     = (const float*)d_in[5];
    const float* b2     = (const float*)d_in[6];
    const float* W3     = (const float*)d_in[7];
    const float* b3     = (const float*)d_in[8];
    float* out = (float*)d_out;

    static CUtensorMap tAhi, tAlo, tBh, tBl;
    static bool init_done = false;
    if (!init_done) {
        cudaFuncSetAttribute(gemm_tma_kernel,
                             cudaFuncAttributeMaxDynamicSharedMemorySize, SMEM_GEMM);
        tme_fn enc = nullptr;
        cudaDriverEntryPointQueryResult qr;
        cudaGetDriverEntryPointByVersion("cuTensorMapEncodeTiled", (void**)&enc,
                                         12000, cudaEnableDefault, &qr);
        void *pAhi, *pAlo, *pBh, *pBl;
        cudaGetSymbolAddress(&pAhi, g_Ahi);
        cudaGetSymbolAddress(&pAlo, g_Alo);
        cudaGetSymbolAddress(&pBh, g_Bh);
        cudaGetSymbolAddress(&pBl, g_Bl);

        cuuint64_t dimsA[2] = {1024, 4096};
        cuuint64_t strA[1]  = {2048};
        cuuint32_t boxA[2]  = {64, 112};
        cuuint32_t es[2]    = {1, 1};
        enc(&tAhi, CU_TENSOR_MAP_DATA_TYPE_UINT16, 2, pAhi, dimsA, strA, boxA, es,
            CU_TENSOR_MAP_INTERLEAVE_NONE, CU_TENSOR_MAP_SWIZZLE_128B,
            CU_TENSOR_MAP_L2_PROMOTION_L2_128B, CU_TENSOR_MAP_FLOAT_OOB_FILL_NONE);
        enc(&tAlo, CU_TENSOR_MAP_DATA_TYPE_UINT16, 2, pAlo, dimsA, strA, boxA, es,
            CU_TENSOR_MAP_INTERLEAVE_NONE, CU_TENSOR_MAP_SWIZZLE_128B,
            CU_TENSOR_MAP_L2_PROMOTION_L2_128B, CU_TENSOR_MAP_FLOAT_OOB_FILL_NONE);

        cuuint64_t dimsB[2] = {1024, 1024};
        cuuint64_t strB[1]  = {2048};
        cuuint32_t boxB[2]  = {64, 64};
        enc(&tBh, CU_TENSOR_MAP_DATA_TYPE_UINT16, 2, pBh, dimsB, strB, boxB, es,
            CU_TENSOR_MAP_INTERLEAVE_NONE, CU_TENSOR_MAP_SWIZZLE_128B,
            CU_TENSOR_MAP_L2_PROMOTION_L2_128B, CU_TENSOR_MAP_FLOAT_OOB_FILL_NONE);
        enc(&tBl, CU_TENSOR_MAP_DATA_TYPE_UINT16, 2, pBl, dimsB, strB, boxB, es,
            CU_TENSOR_MAP_INTERLEAVE_NONE, CU_TENSOR_MAP_SWIZZLE_128B,
            CU_TENSOR_MAP_L2_PROMOTION_L2_128B, CU_TENSOR_MAP_FLOAT_OOB_FILL_NONE);
        init_done = true;
    }

    prep_kernel<<<4305, 256>>>(X, weight, W1, b1);                      // 1
    fold_kernel<<<8, 256>>>();                                          // 2
    mlp_kernel<<<N_U, 256>>>(weight, W2, b2, W3, b3);                   // 3
    gemm_tma_kernel<<<148, 512, SMEM_GEMM>>>(tAhi, tAlo, tBh, tBl, out);// 4
    softmax_kernel<<<BATCH, 256>>>(out);                                // 5
}